// round 3
// baseline (speedup 1.0000x reference)
#include <cuda_runtime.h>
#include <cstdint>

// Problem constants (shapes are fixed by the dataset)
#define NS_MAX 100000
#define NP_MAX 20000
#define E_MAX  500000
#define HF 128   // F == H == 128

// ---------------- scratch (device globals; no allocation allowed) -------------
__device__ float g_xplay[NP_MAX * HF];
__device__ float g_aggP [NP_MAX * HF];
__device__ float g_aggS [NS_MAX * HF];
__device__ float g_p1   [NP_MAX * HF];
__device__ float g_s1   [NS_MAX * HF];
__device__ int   g_cntP [NP_MAX];
__device__ int   g_cntS [NS_MAX];
__device__ int   g_offP [NP_MAX + 1];
__device__ int   g_offS [NS_MAX + 1];
__device__ int   g_curP [NP_MAX];
__device__ int   g_curS [NS_MAX];
__device__ float g_invP [NP_MAX];
__device__ float g_invS [NS_MAX];
__device__ int   g_adjP [E_MAX];   // for each playlist: source song ids
__device__ int   g_adjS [E_MAX];   // for each song: source playlist ids

// ---------------- degree histogram (both directions fused) --------------------
__global__ void count_kernel(const int* __restrict__ es, const int* __restrict__ ep,
                             int* __restrict__ cntS, int* __restrict__ cntP, int E) {
    int i = blockIdx.x * blockDim.x + threadIdx.x;
    if (i >= E) return;
    atomicAdd(&cntS[es[i]], 1);
    atomicAdd(&cntP[ep[i]], 1);
}

// ---------------- single-block exclusive scan (4 items/thread) ---------------
__device__ void scan_block(const int* __restrict__ cnt, int* __restrict__ off, int n) {
    __shared__ int wsum[32];
    __shared__ int carry;
    const int tid = threadIdx.x;
    const int lane = tid & 31, wid = tid >> 5;
    if (tid == 0) { carry = 0; off[0] = 0; }
    __syncthreads();
    const int CH = 4;
    const int step = blockDim.x * CH;
    for (int base = 0; base < n; base += step) {
        int i0 = base + tid * CH;
        int v[CH];
        #pragma unroll
        for (int k = 0; k < CH; k++) v[k] = (i0 + k < n) ? cnt[i0 + k] : 0;
        int t = v[0] + v[1] + v[2] + v[3];
        int x = t;
        #pragma unroll
        for (int d = 1; d < 32; d <<= 1) {
            int y = __shfl_up_sync(0xffffffffu, x, d);
            if (lane >= d) x += y;
        }
        if (lane == 31) wsum[wid] = x;
        __syncthreads();
        if (wid == 0) {
            int ws = (lane < (int)(blockDim.x >> 5)) ? wsum[lane] : 0;
            #pragma unroll
            for (int d = 1; d < 32; d <<= 1) {
                int y = __shfl_up_sync(0xffffffffu, ws, d);
                if (lane >= d) ws += y;
            }
            wsum[lane] = ws;
        }
        __syncthreads();
        int incl = x + (wid > 0 ? wsum[wid - 1] : 0) + carry;
        int run = incl - t;  // exclusive prefix for this thread's first item
        #pragma unroll
        for (int k = 0; k < CH; k++) {
            run += v[k];
            if (i0 + k < n) off[i0 + k + 1] = run;
        }
        __syncthreads();
        if (tid == blockDim.x - 1) carry = incl;
        __syncthreads();
    }
}

__global__ void scan2_kernel(const int* cntP, int* offP, int nP,
                             const int* cntS, int* offS, int nS) {
    if (blockIdx.x == 0) scan_block(cntP, offP, nP);
    else                 scan_block(cntS, offS, nS);
}

// ---------------- CSR fill (both directions fused) ----------------------------
__global__ void fill_kernel(const int* __restrict__ es, const int* __restrict__ ep,
                            const int* __restrict__ offS, const int* __restrict__ offP,
                            int* __restrict__ curS, int* __restrict__ curP,
                            int* __restrict__ adjS, int* __restrict__ adjP, int E) {
    int i = blockIdx.x * blockDim.x + threadIdx.x;
    if (i >= E) return;
    int s = es[i], p = ep[i];
    int ps = atomicAdd(&curS[s], 1);
    adjS[offS[s] + ps] = p;
    int pp = atomicAdd(&curP[p], 1);
    adjP[offP[p] + pp] = s;
}

// ---------------- 1/max(deg,1) -----------------------------------------------
__global__ void inv_kernel(const int* __restrict__ cntP, float* __restrict__ invP, int nP,
                           const int* __restrict__ cntS, float* __restrict__ invS, int nS) {
    int i = blockIdx.x * blockDim.x + threadIdx.x;
    if (i < nP) invP[i] = 1.0f / (float)max(cntP[i], 1);
    if (i < nS) invS[i] = 1.0f / (float)max(cntS[i], 1);
}

// ---------------- playlist embedding gather -----------------------------------
__global__ void gather_play(const float* __restrict__ pe, const int* __restrict__ pid,
                            float* __restrict__ out, int NP) {
    int t = blockIdx.x * blockDim.x + threadIdx.x;
    int row = t >> 5, lane = t & 31;
    if (row >= NP) return;
    const float4* src = (const float4*)(pe + (size_t)pid[row] * HF);
    ((float4*)(out + (size_t)row * HF))[lane] = __ldg(src + lane);
}

// ---------------- CSR mean-aggregation: warp per destination node -------------
__global__ void csr_agg(const float* __restrict__ src,   // [*,128] feature rows
                        const int* __restrict__ off, const int* __restrict__ adj,
                        const float* __restrict__ inv,
                        float* __restrict__ out, int Ndst) {
    int warp = (blockIdx.x * blockDim.x + threadIdx.x) >> 5;
    int lane = threadIdx.x & 31;
    if (warp >= Ndst) return;
    int s0 = off[warp], s1 = off[warp + 1];
    float4 acc = make_float4(0.f, 0.f, 0.f, 0.f);
    for (int e = s0; e < s1; e += 32) {
        int myE = e + lane;
        int myIdx = (myE < s1) ? __ldg(adj + myE) : 0;
        int cnt = min(32, s1 - e);
        for (int j = 0; j < cnt; j++) {
            int sidx = __shfl_sync(0xffffffffu, myIdx, j);
            float4 v = __ldg(((const float4*)src) + (size_t)sidx * 32 + lane);
            acc.x += v.x; acc.y += v.y; acc.z += v.z; acc.w += v.w;
        }
    }
    float w = inv[warp];
    acc.x *= w; acc.y *= w; acc.z *= w; acc.w *= w;
    ((float4*)(out + (size_t)warp * HF))[lane] = acc;
}

// ---------------- fused dual GEMM: out = act(A1@W1 + b + A2@W2) ---------------
// A1, A2: [N,128] row-major.  W1, W2: [128,128] row-major.  K "virtual" = 256.
__global__ __launch_bounds__(256)
void dual_gemm(const float* __restrict__ A1, const float* __restrict__ A2,
               const float* __restrict__ W1, const float* __restrict__ W2,
               const float* __restrict__ bias, float* __restrict__ out,
               int N, int doRelu) {
    __shared__ float As[128][16];   // [row][k] within tile
    __shared__ float Bs[16][128];   // [k][col]
    const int tid = threadIdx.x;
    const int trow = (tid >> 4) << 3;   // (tid/16)*8
    const int tcol = (tid & 15) << 3;   // (tid%16)*8
    const int rowBase = blockIdx.x * 128;

    float acc[8][8];
    #pragma unroll
    for (int i = 0; i < 8; i++)
        #pragma unroll
        for (int j = 0; j < 8; j++) acc[i][j] = 0.f;

    #pragma unroll 1
    for (int t = 0; t < 16; t++) {
        const float* A = (t < 8) ? A1 : A2;
        const float* W = (t < 8) ? W1 : W2;
        const int k0 = (t & 7) * 16;
        // load A tile: 128x16 floats, 512 float4 chunks / 256 threads
        #pragma unroll
        for (int u = 0; u < 2; u++) {
            int c = tid + u * 256;
            int r = c >> 2, kc = (c & 3) << 2;
            int gr = rowBase + r;
            float4 v = make_float4(0.f, 0.f, 0.f, 0.f);
            if (gr < N) v = *(const float4*)(A + (size_t)gr * 128 + k0 + kc);
            *(float4*)(&As[r][kc]) = v;
        }
        // load B tile: 16x128 floats
        #pragma unroll
        for (int u = 0; u < 2; u++) {
            int c = tid + u * 256;
            int kk = c >> 5, col = (c & 31) << 2;
            float4 v = *(const float4*)(W + (size_t)(k0 + kk) * 128 + col);
            *(float4*)(&Bs[kk][col]) = v;
        }
        __syncthreads();
        #pragma unroll
        for (int kk = 0; kk < 16; kk++) {
            float a[8];
            #pragma unroll
            for (int i = 0; i < 8; i++) a[i] = As[trow + i][kk];
            float4 b0 = *(const float4*)(&Bs[kk][tcol]);
            float4 b1 = *(const float4*)(&Bs[kk][tcol + 4]);
            float b[8] = {b0.x, b0.y, b0.z, b0.w, b1.x, b1.y, b1.z, b1.w};
            #pragma unroll
            for (int i = 0; i < 8; i++)
                #pragma unroll
                for (int j = 0; j < 8; j++)
                    acc[i][j] += a[i] * b[j];
        }
        __syncthreads();
    }
    // epilogue: bias (+ relu), fp32 store
    float bb[8];
    #pragma unroll
    for (int j = 0; j < 8; j++) bb[j] = bias[tcol + j];
    #pragma unroll
    for (int i = 0; i < 8; i++) {
        int gr = rowBase + trow + i;
        if (gr < N) {
            float v[8];
            #pragma unroll
            for (int j = 0; j < 8; j++) {
                float x = acc[i][j] + bb[j];
                v[j] = doRelu ? fmaxf(x, 0.f) : x;
            }
            *(float4*)(out + (size_t)gr * 128 + tcol)     = make_float4(v[0], v[1], v[2], v[3]);
            *(float4*)(out + (size_t)gr * 128 + tcol + 4) = make_float4(v[4], v[5], v[6], v[7]);
        }
    }
}

// ---------------- launch ------------------------------------------------------
extern "C" void kernel_launch(void* const* d_in, const int* in_sizes, int n_in,
                              void* d_out, int out_size) {
    const float* song_x = (const float*)d_in[0];
    const int*   pid    = (const int*)  d_in[1];
    const int*   es     = (const int*)  d_in[2];   // edge_song  (song endpoint)
    const int*   ep     = (const int*)  d_in[3];   // edge_playlist
    const float* pemb   = (const float*)d_in[4];
    const float* Wl1_sp = (const float*)d_in[5];
    const float* Wr1_sp = (const float*)d_in[6];
    const float* b1_sp  = (const float*)d_in[7];
    const float* Wl1_ps = (const float*)d_in[8];
    const float* Wr1_ps = (const float*)d_in[9];
    const float* b1_ps  = (const float*)d_in[10];
    const float* Wl2_sp = (const float*)d_in[11];
    const float* Wr2_sp = (const float*)d_in[12];
    const float* b2_sp  = (const float*)d_in[13];
    const float* Wl2_ps = (const float*)d_in[14];
    const float* Wr2_ps = (const float*)d_in[15];
    const float* b2_ps  = (const float*)d_in[16];

    const int NS = in_sizes[0] / HF;
    const int NP = in_sizes[1];
    const int E  = in_sizes[2];

    float *xplay, *aggP, *aggS, *p1, *s1, *invP, *invS;
    int *cntP, *cntS, *offP, *offS, *curP, *curS, *adjP, *adjS;
    cudaGetSymbolAddress((void**)&xplay, g_xplay);
    cudaGetSymbolAddress((void**)&aggP,  g_aggP);
    cudaGetSymbolAddress((void**)&aggS,  g_aggS);
    cudaGetSymbolAddress((void**)&p1,    g_p1);
    cudaGetSymbolAddress((void**)&s1,    g_s1);
    cudaGetSymbolAddress((void**)&invP,  g_invP);
    cudaGetSymbolAddress((void**)&invS,  g_invS);
    cudaGetSymbolAddress((void**)&cntP,  g_cntP);
    cudaGetSymbolAddress((void**)&cntS,  g_cntS);
    cudaGetSymbolAddress((void**)&offP,  g_offP);
    cudaGetSymbolAddress((void**)&offS,  g_offS);
    cudaGetSymbolAddress((void**)&curP,  g_curP);
    cudaGetSymbolAddress((void**)&curS,  g_curS);
    cudaGetSymbolAddress((void**)&adjP,  g_adjP);
    cudaGetSymbolAddress((void**)&adjS,  g_adjS);

    float* out_s2 = (float*)d_out;                       // [NS,128]
    float* out_p2 = (float*)d_out + (size_t)NS * HF;     // [NP,128]

    // ---- graph-structure build (per launch, deterministic work) ----
    cudaMemsetAsync(cntP, 0, NP * sizeof(int), 0);
    cudaMemsetAsync(cntS, 0, NS * sizeof(int), 0);
    cudaMemsetAsync(curP, 0, NP * sizeof(int), 0);
    cudaMemsetAsync(curS, 0, NS * sizeof(int), 0);

    count_kernel<<<(E + 255) / 256, 256>>>(es, ep, cntS, cntP, E);
    scan2_kernel<<<2, 1024>>>(cntP, offP, NP, cntS, offS, NS);
    fill_kernel<<<(E + 255) / 256, 256>>>(es, ep, offS, offP, curS, curP, adjS, adjP, E);
    {
        int nmax = NS > NP ? NS : NP;
        inv_kernel<<<(nmax + 255) / 256, 256>>>(cntP, invP, NP, cntS, invS, NS);
    }
    gather_play<<<(NP * 32 + 255) / 256, 256>>>(pemb, pid, xplay, NP);

    const int aggBlkP = (NP + 7) / 8;   // 8 warps/block
    const int aggBlkS = (NS + 7) / 8;
    const int gemmBlkP = (NP + 127) / 128;
    const int gemmBlkS = (NS + 127) / 128;

    // ---- layer 1 ----
    csr_agg<<<aggBlkP, 256>>>(song_x, offP, adjP, invP, aggP, NP);
    dual_gemm<<<gemmBlkP, 256>>>(aggP, xplay, Wl1_sp, Wr1_sp, b1_sp, p1, NP, 1);

    csr_agg<<<aggBlkS, 256>>>(xplay, offS, adjS, invS, aggS, NS);
    dual_gemm<<<gemmBlkS, 256>>>(aggS, song_x, Wl1_ps, Wr1_ps, b1_ps, s1, NS, 1);

    // ---- layer 2 ----
    csr_agg<<<aggBlkP, 256>>>(s1, offP, adjP, invP, aggP, NP);
    dual_gemm<<<gemmBlkP, 256>>>(aggP, p1, Wl2_sp, Wr2_sp, b2_sp, out_p2, NP, 0);

    csr_agg<<<aggBlkS, 256>>>(p1, offS, adjS, invS, aggS, NS);
    dual_gemm<<<gemmBlkS, 256>>>(aggS, s1, Wl2_ps, Wr2_ps, b2_ps, out_s2, NS, 0);
}

// round 6
// speedup vs baseline: 1.5183x; 1.5183x over previous
#include <cuda_runtime.h>
#include <cuda_bf16.h>
#include <cstdint>

#define NS_MAX 100000
#define NP_MAX 20000
#define E_MAX  500000
#define HF 128

// ======================= device scratch (no allocation allowed) ==============
__device__ float g_xplay[NP_MAX * HF];
__device__ float g_p1   [NP_MAX * HF];
__device__ float g_s1   [NS_MAX * HF];

__device__ __nv_bfloat16 g_songHi[NS_MAX * HF], g_songLo[NS_MAX * HF];
__device__ __nv_bfloat16 g_playHi[NP_MAX * HF], g_playLo[NP_MAX * HF];
__device__ __nv_bfloat16 g_aggPHi[NP_MAX * HF], g_aggPLo[NP_MAX * HF];
__device__ __nv_bfloat16 g_aggSHi[NS_MAX * HF], g_aggSLo[NS_MAX * HF];
__device__ __nv_bfloat16 g_p1Hi  [NP_MAX * HF], g_p1Lo  [NP_MAX * HF];
__device__ __nv_bfloat16 g_s1Hi  [NS_MAX * HF], g_s1Lo  [NS_MAX * HF];
__device__ __nv_bfloat16 g_WHi[4][HF * 256], g_WLo[4][HF * 256];  // B[n][k], k = concat(Wl,Wr)

__device__ int   g_cntP[NP_MAX], g_cntS[NS_MAX];
__device__ int   g_offP[NP_MAX + 1], g_offS[NS_MAX + 1];
__device__ int   g_curP[NP_MAX], g_curS[NS_MAX];
__device__ float g_invP[NP_MAX], g_invS[NS_MAX];
__device__ int   g_adjP[E_MAX], g_adjS[E_MAX];

// ======================= helpers =============================================
__device__ __forceinline__ uint32_t smem_u32(const void* p) {
    uint32_t a;
    asm("{ .reg .u64 t; cvta.to.shared.u64 t, %1; cvt.u32.u64 %0, t; }" : "=r"(a) : "l"(p));
    return a;
}
__device__ __forceinline__ uint32_t pack2bf(__nv_bfloat16 a, __nv_bfloat16 b) {
    return (uint32_t)__bfloat16_as_ushort(a) | ((uint32_t)__bfloat16_as_ushort(b) << 16);
}
__device__ __forceinline__ void split_f32(float x, __nv_bfloat16& h, __nv_bfloat16& l) {
    h = __float2bfloat16(x);
    l = __float2bfloat16(x - __bfloat162float(h));
}
__device__ __forceinline__ void ldsm_x4(uint32_t* r, uint32_t addr) {
    asm volatile("ldmatrix.sync.aligned.m8n8.x4.shared.b16 {%0,%1,%2,%3}, [%4];"
                 : "=r"(r[0]), "=r"(r[1]), "=r"(r[2]), "=r"(r[3]) : "r"(addr));
}
__device__ __forceinline__ void ldsm_x2(uint32_t* r, uint32_t addr) {
    asm volatile("ldmatrix.sync.aligned.m8n8.x2.shared.b16 {%0,%1}, [%2];"
                 : "=r"(r[0]), "=r"(r[1]) : "r"(addr));
}
__device__ __forceinline__ void mma_bf16(float* d, const uint32_t* a, const uint32_t* b) {
    asm volatile("mma.sync.aligned.m16n8k16.row.col.f32.bf16.bf16.f32 "
                 "{%0,%1,%2,%3}, {%4,%5,%6,%7}, {%8,%9}, {%0,%1,%2,%3};"
                 : "+f"(d[0]), "+f"(d[1]), "+f"(d[2]), "+f"(d[3])
                 : "r"(a[0]), "r"(a[1]), "r"(a[2]), "r"(a[3]), "r"(b[0]), "r"(b[1]));
}

// ======================= graph-structure build ===============================
__global__ void count_kernel(const int* __restrict__ es, const int* __restrict__ ep,
                             int* __restrict__ cntS, int* __restrict__ cntP, int E) {
    int i = blockIdx.x * blockDim.x + threadIdx.x;
    if (i >= E) return;
    atomicAdd(&cntS[es[i]], 1);
    atomicAdd(&cntP[ep[i]], 1);
}

__device__ void scan_block(const int* __restrict__ cnt, int* __restrict__ off, int n) {
    __shared__ int wsum[32];
    __shared__ int carry;
    const int tid = threadIdx.x, lane = tid & 31, wid = tid >> 5;
    if (tid == 0) { carry = 0; off[0] = 0; }
    __syncthreads();
    const int CH = 4, step = blockDim.x * CH;
    for (int base = 0; base < n; base += step) {
        int i0 = base + tid * CH;
        int v[CH];
        #pragma unroll
        for (int k = 0; k < CH; k++) v[k] = (i0 + k < n) ? cnt[i0 + k] : 0;
        int t = v[0] + v[1] + v[2] + v[3];
        int x = t;
        #pragma unroll
        for (int d = 1; d < 32; d <<= 1) { int y = __shfl_up_sync(~0u, x, d); if (lane >= d) x += y; }
        if (lane == 31) wsum[wid] = x;
        __syncthreads();
        if (wid == 0) {
            int ws = (lane < (int)(blockDim.x >> 5)) ? wsum[lane] : 0;
            #pragma unroll
            for (int d = 1; d < 32; d <<= 1) { int y = __shfl_up_sync(~0u, ws, d); if (lane >= d) ws += y; }
            wsum[lane] = ws;
        }
        __syncthreads();
        int incl = x + (wid > 0 ? wsum[wid - 1] : 0) + carry;
        int run = incl - t;
        #pragma unroll
        for (int k = 0; k < CH; k++) { run += v[k]; if (i0 + k < n) off[i0 + k + 1] = run; }
        __syncthreads();
        if (tid == blockDim.x - 1) carry = incl;
        __syncthreads();
    }
}
__global__ void scan2_kernel(const int* cntP, int* offP, int nP,
                             const int* cntS, int* offS, int nS) {
    if (blockIdx.x == 0) scan_block(cntP, offP, nP);
    else                 scan_block(cntS, offS, nS);
}
__global__ void fill_kernel(const int* __restrict__ es, const int* __restrict__ ep,
                            const int* __restrict__ offS, const int* __restrict__ offP,
                            int* __restrict__ curS, int* __restrict__ curP,
                            int* __restrict__ adjS, int* __restrict__ adjP, int E) {
    int i = blockIdx.x * blockDim.x + threadIdx.x;
    if (i >= E) return;
    int s = es[i], p = ep[i];
    int ps = atomicAdd(&curS[s], 1); adjS[offS[s] + ps] = p;
    int pp = atomicAdd(&curP[p], 1); adjP[offP[p] + pp] = s;
}
__global__ void inv_kernel(const int* __restrict__ cntP, float* __restrict__ invP, int nP,
                           const int* __restrict__ cntS, float* __restrict__ invS, int nS) {
    int i = blockIdx.x * blockDim.x + threadIdx.x;
    if (i < nP) invP[i] = 1.0f / (float)max(cntP[i], 1);
    if (i < nS) invS[i] = 1.0f / (float)max(cntS[i], 1);
}

// ======================= input conversions ===================================
__global__ void gather_play(const float* __restrict__ pe, const int* __restrict__ pid,
                            float* __restrict__ outF,
                            __nv_bfloat16* __restrict__ outHi, __nv_bfloat16* __restrict__ outLo,
                            int NP) {
    int t = blockIdx.x * blockDim.x + threadIdx.x;
    int row = t >> 5, lane = t & 31;
    if (row >= NP) return;
    float4 v = __ldg((const float4*)(pe + (size_t)pid[row] * HF) + lane);
    ((float4*)(outF + (size_t)row * HF))[lane] = v;
    __nv_bfloat16 h0,h1,h2,h3,l0,l1,l2,l3;
    split_f32(v.x,h0,l0); split_f32(v.y,h1,l1); split_f32(v.z,h2,l2); split_f32(v.w,h3,l3);
    ((uint2*)(outHi + (size_t)row * HF))[lane] = make_uint2(pack2bf(h0,h1), pack2bf(h2,h3));
    ((uint2*)(outLo + (size_t)row * HF))[lane] = make_uint2(pack2bf(l0,l1), pack2bf(l2,l3));
}

__global__ void convert_f32(const float* __restrict__ in,
                            __nv_bfloat16* __restrict__ outHi, __nv_bfloat16* __restrict__ outLo,
                            int n4) {
    int i = blockIdx.x * blockDim.x + threadIdx.x;
    if (i >= n4) return;
    float4 v = __ldg((const float4*)in + i);
    __nv_bfloat16 h0,h1,h2,h3,l0,l1,l2,l3;
    split_f32(v.x,h0,l0); split_f32(v.y,h1,l1); split_f32(v.z,h2,l2); split_f32(v.w,h3,l3);
    ((uint2*)outHi)[i] = make_uint2(pack2bf(h0,h1), pack2bf(h2,h3));
    ((uint2*)outLo)[i] = make_uint2(pack2bf(l0,l1), pack2bf(l2,l3));
}

// weights: B[n][k] = concat(Wl, Wr)[k][n], split hi/lo.  blockIdx.y = pair id.
__global__ void prep_weights(const float* Wl0, const float* Wr0, const float* Wl1, const float* Wr1,
                             const float* Wl2, const float* Wr2, const float* Wl3, const float* Wr3,
                             __nv_bfloat16* __restrict__ WHi, __nv_bfloat16* __restrict__ WLo) {
    int pair = blockIdx.y;
    const float* Wl = pair == 0 ? Wl0 : pair == 1 ? Wl1 : pair == 2 ? Wl2 : Wl3;
    const float* Wr = pair == 0 ? Wr0 : pair == 1 ? Wr1 : pair == 2 ? Wr2 : Wr3;
    int idx = blockIdx.x * blockDim.x + threadIdx.x;
    if (idx >= HF * 256) return;
    int k = idx & 255, n = idx >> 8;
    float w = (k < 128) ? Wl[(size_t)k * HF + n] : Wr[(size_t)(k - 128) * HF + n];
    __nv_bfloat16 h, l; split_f32(w, h, l);
    WHi[(size_t)pair * HF * 256 + (size_t)n * 256 + k] = h;
    WLo[(size_t)pair * HF * 256 + (size_t)n * 256 + k] = l;
}

// ======================= CSR mean-aggregation (fp32 in, bf16 hi/lo out) ======
__global__ void csr_agg(const float* __restrict__ src,
                        const int* __restrict__ off, const int* __restrict__ adj,
                        const float* __restrict__ inv,
                        __nv_bfloat16* __restrict__ outHi, __nv_bfloat16* __restrict__ outLo,
                        int Ndst) {
    int warp = (blockIdx.x * blockDim.x + threadIdx.x) >> 5;
    int lane = threadIdx.x & 31;
    if (warp >= Ndst) return;
    int s0 = off[warp], s1 = off[warp + 1];
    float4 acc = make_float4(0.f, 0.f, 0.f, 0.f);
    for (int e = s0; e < s1; e += 32) {
        int myE = e + lane;
        int myIdx = (myE < s1) ? __ldg(adj + myE) : 0;
        int cnt = min(32, s1 - e);
        for (int j = 0; j < cnt; j++) {
            int sidx = __shfl_sync(~0u, myIdx, j);
            float4 v = __ldg(((const float4*)src) + (size_t)sidx * 32 + lane);
            acc.x += v.x; acc.y += v.y; acc.z += v.z; acc.w += v.w;
        }
    }
    float w = inv[warp];
    acc.x *= w; acc.y *= w; acc.z *= w; acc.w *= w;
    __nv_bfloat16 h0,h1,h2,h3,l0,l1,l2,l3;
    split_f32(acc.x,h0,l0); split_f32(acc.y,h1,l1); split_f32(acc.z,h2,l2); split_f32(acc.w,h3,l3);
    ((uint2*)(outHi + (size_t)warp * HF))[lane] = make_uint2(pack2bf(h0,h1), pack2bf(h2,h3));
    ((uint2*)(outLo + (size_t)warp * HF))[lane] = make_uint2(pack2bf(l0,l1), pack2bf(l2,l3));
}

// ======================= mma.sync split-bf16 dual GEMM =======================
// out = act(A1 @ Wl + b + A2 @ Wr).  Block tile 128x128, K-concat 256 in 4
// chunks of 64.  3 accumulating passes per chunk: Ah*Bh, Ah*Bl, Al*Bh.
// SMEM: 4 x 16KB XOR-swizzled buffers (Ah, Al, Bh, Bl).
#define GEMM_SMEM 65536
#define OFF_AH 0
#define OFF_AL 16384
#define OFF_BH 32768
#define OFF_BL 49152

__device__ __forceinline__ int sw_off(int r, int q) {      // r: row 0..127, q: 16B group 0..7
    return r * 128 + ((q ^ (r & 7)) << 4);
}

__global__ __launch_bounds__(256, 2)
void mma_dual_gemm(const __nv_bfloat16* __restrict__ A1Hi, const __nv_bfloat16* __restrict__ A1Lo,
                   const __nv_bfloat16* __restrict__ A2Hi, const __nv_bfloat16* __restrict__ A2Lo,
                   const __nv_bfloat16* __restrict__ BHi,  const __nv_bfloat16* __restrict__ BLo,
                   const float* __restrict__ bias,
                   float* __restrict__ outF,
                   __nv_bfloat16* __restrict__ outHi, __nv_bfloat16* __restrict__ outLo,
                   int N, int doRelu) {
    extern __shared__ char smem[];
    const uint32_t sb = smem_u32(smem);
    const int tid = threadIdx.x, wid = tid >> 5, lane = tid & 31;
    const int rowBase = blockIdx.x * 128;

    // warp tiling: 4 warps along M (32 rows each), 2 along N (64 cols each)
    const int mBase = (wid & 3) * 32;
    const int nBase = (wid >> 2) * 64;

    float acc[2][8][4];
    #pragma unroll
    for (int mt = 0; mt < 2; mt++)
        #pragma unroll
        for (int nt = 0; nt < 8; nt++)
            #pragma unroll
            for (int j = 0; j < 4; j++) acc[mt][nt][j] = 0.f;

    // precomputed per-lane ldmatrix address components
    const int rowA = mBase + (lane & 15);       // + mt*16
    const int partA = lane >> 4;                // 0/1 -> +8 elems (16B)
    const int swA = rowA & 7;
    const int rowB0 = nBase + (lane & 7);       // + nt*8
    const int partB = (lane >> 3) & 1;
    const int swB = lane & 7;

    #pragma unroll 1
    for (int c = 0; c < 4; c++) {
        const __nv_bfloat16* AH = (c < 2) ? A1Hi : A2Hi;
        const __nv_bfloat16* AL = (c < 2) ? A1Lo : A2Lo;
        const int kA = (c & 1) * 64;
        const int kB = c * 64;

        __syncthreads();   // previous chunk's compute done -> smem reusable
        #pragma unroll
        for (int u = 0; u < 4; u++) {
            int idx = tid + u * 256;
            int r = idx >> 3, q = idx & 7;
            int gr = rowBase + r;
            uint4 vah, val;
            if (gr < N) {
                vah = __ldg((const uint4*)(AH + (size_t)gr * HF + kA) + q);
                val = __ldg((const uint4*)(AL + (size_t)gr * HF + kA) + q);
            } else { vah = make_uint4(0,0,0,0); val = vah; }
            uint4 vbh = __ldg((const uint4*)(BHi + (size_t)r * 256 + kB) + q);
            uint4 vbl = __ldg((const uint4*)(BLo + (size_t)r * 256 + kB) + q);
            int so = sw_off(r, q);
            *(uint4*)(smem + OFF_AH + so) = vah;
            *(uint4*)(smem + OFF_AL + so) = val;
            *(uint4*)(smem + OFF_BH + so) = vbh;
            *(uint4*)(smem + OFF_BL + so) = vbl;
        }
        __syncthreads();

        #pragma unroll
        for (int pass = 0; pass < 3; pass++) {
            const uint32_t aB = sb + (pass == 2 ? OFF_AL : OFF_AH);
            const uint32_t bB = sb + (pass == 1 ? OFF_BL : OFF_BH);
            #pragma unroll
            for (int ks = 0; ks < 4; ks++) {
                uint32_t a[2][4], b[8][2];
                const int qa = ks * 2 + partA;
                #pragma unroll
                for (int mt = 0; mt < 2; mt++)
                    ldsm_x4(a[mt], aB + (rowA + mt * 16) * 128 + ((qa ^ swA) << 4));
                const int qb = ks * 2 + partB;
                #pragma unroll
                for (int nt = 0; nt < 8; nt++)
                    ldsm_x2(b[nt], bB + (rowB0 + nt * 8) * 128 + ((qb ^ swB) << 4));
                #pragma unroll
                for (int mt = 0; mt < 2; mt++)
                    #pragma unroll
                    for (int nt = 0; nt < 8; nt++)
                        mma_bf16(acc[mt][nt], a[mt], b[nt]);
            }
        }
    }

    // ---- epilogue: bias (+relu), fp32 store, optional bf16 hi/lo split ------
    const int erow = lane >> 2;               // 0..7
    const int ecol = (lane & 3) * 2;          // 0,2,4,6
    #pragma unroll
    for (int mt = 0; mt < 2; mt++) {
        #pragma unroll
        for (int nt = 0; nt < 8; nt++) {
            int col = nBase + nt * 8 + ecol;
            float2 bb = *(const float2*)(bias + col);
            #pragma unroll
            for (int h = 0; h < 2; h++) {     // h=0: rows r, h=1: rows r+8
                int gr = rowBase + mBase + mt * 16 + erow + h * 8;
                if (gr < N) {
                    float x0 = acc[mt][nt][h * 2 + 0] + bb.x;
                    float x1 = acc[mt][nt][h * 2 + 1] + bb.y;
                    if (doRelu) { x0 = fmaxf(x0, 0.f); x1 = fmaxf(x1, 0.f); }
                    *(float2*)(outF + (size_t)gr * HF + col) = make_float2(x0, x1);
                    if (outHi) {
                        __nv_bfloat16 h0, h1, l0, l1;
                        split_f32(x0, h0, l0); split_f32(x1, h1, l1);
                        *(uint32_t*)(outHi + (size_t)gr * HF + col) = pack2bf(h0, h1);
                        *(uint32_t*)(outLo + (size_t)gr * HF + col) = pack2bf(l0, l1);
                    }
                }
            }
        }
    }
}

// ======================= launch =============================================
extern "C" void kernel_launch(void* const* d_in, const int* in_sizes, int n_in,
                              void* d_out, int out_size) {
    const float* song_x = (const float*)d_in[0];
    const int*   pid    = (const int*)  d_in[1];
    const int*   es     = (const int*)  d_in[2];
    const int*   ep     = (const int*)  d_in[3];
    const float* pemb   = (const float*)d_in[4];
    const float* Wl1_sp = (const float*)d_in[5];
    const float* Wr1_sp = (const float*)d_in[6];
    const float* b1_sp  = (const float*)d_in[7];
    const float* Wl1_ps = (const float*)d_in[8];
    const float* Wr1_ps = (const float*)d_in[9];
    const float* b1_ps  = (const float*)d_in[10];
    const float* Wl2_sp = (const float*)d_in[11];
    const float* Wr2_sp = (const float*)d_in[12];
    const float* b2_sp  = (const float*)d_in[13];
    const float* Wl2_ps = (const float*)d_in[14];
    const float* Wr2_ps = (const float*)d_in[15];
    const float* b2_ps  = (const float*)d_in[16];

    const int NS = in_sizes[0] / HF;
    const int NP = in_sizes[1];
    const int E  = in_sizes[2];

    float *xplay, *p1, *s1, *invP, *invS;
    int *cntP, *cntS, *offP, *offS, *curP, *curS, *adjP, *adjS;
    __nv_bfloat16 *songHi,*songLo,*playHi,*playLo,*aggPHi,*aggPLo,*aggSHi,*aggSLo,*p1Hi,*p1Lo,*s1Hi,*s1Lo,*WHi,*WLo;
    cudaGetSymbolAddress((void**)&xplay, g_xplay);
    cudaGetSymbolAddress((void**)&p1,    g_p1);
    cudaGetSymbolAddress((void**)&s1,    g_s1);
    cudaGetSymbolAddress((void**)&invP,  g_invP);
    cudaGetSymbolAddress((void**)&invS,  g_invS);
    cudaGetSymbolAddress((void**)&cntP,  g_cntP);
    cudaGetSymbolAddress((void**)&cntS,  g_cntS);
    cudaGetSymbolAddress((void**)&offP,  g_offP);
    cudaGetSymbolAddress((void**)&offS,  g_offS);
    cudaGetSymbolAddress((void**)&curP,  g_curP);
    cudaGetSymbolAddress((void**)&curS,  g_curS);
    cudaGetSymbolAddress((void**)&adjP,  g_adjP);
    cudaGetSymbolAddress((void**)&adjS,  g_adjS);
    cudaGetSymbolAddress((void**)&songHi, g_songHi); cudaGetSymbolAddress((void**)&songLo, g_songLo);
    cudaGetSymbolAddress((void**)&playHi, g_playHi); cudaGetSymbolAddress((void**)&playLo, g_playLo);
    cudaGetSymbolAddress((void**)&aggPHi, g_aggPHi); cudaGetSymbolAddress((void**)&aggPLo, g_aggPLo);
    cudaGetSymbolAddress((void**)&aggSHi, g_aggSHi); cudaGetSymbolAddress((void**)&aggSLo, g_aggSLo);
    cudaGetSymbolAddress((void**)&p1Hi,   g_p1Hi);   cudaGetSymbolAddress((void**)&p1Lo,   g_p1Lo);
    cudaGetSymbolAddress((void**)&s1Hi,   g_s1Hi);   cudaGetSymbolAddress((void**)&s1Lo,   g_s1Lo);
    cudaGetSymbolAddress((void**)&WHi,    g_WHi);    cudaGetSymbolAddress((void**)&WLo,    g_WLo);

    float* out_s2 = (float*)d_out;
    float* out_p2 = (float*)d_out + (size_t)NS * HF;

    static int smem_set = 0;
    if (!smem_set) {
        cudaFuncSetAttribute(mma_dual_gemm, cudaFuncAttributeMaxDynamicSharedMemorySize, GEMM_SMEM);
        smem_set = 1;
    }

    // ---- graph-structure build ----
    cudaMemsetAsync(cntP, 0, NP * sizeof(int), 0);
    cudaMemsetAsync(cntS, 0, NS * sizeof(int), 0);
    cudaMemsetAsync(curP, 0, NP * sizeof(int), 0);
    cudaMemsetAsync(curS, 0, NS * sizeof(int), 0);
    count_kernel<<<(E + 255) / 256, 256>>>(es, ep, cntS, cntP, E);
    scan2_kernel<<<2, 1024>>>(cntP, offP, NP, cntS, offS, NS);
    fill_kernel<<<(E + 255) / 256, 256>>>(es, ep, offS, offP, curS, curP, adjS, adjP, E);
    {
        int nmax = NS > NP ? NS : NP;
        inv_kernel<<<(nmax + 255) / 256, 256>>>(cntP, invP, NP, cntS, invS, NS);
    }

    // ---- conversions / weight prep ----
    gather_play<<<(NP * 32 + 255) / 256, 256>>>(pemb, pid, xplay, playHi, playLo, NP);
    convert_f32<<<(NS * HF / 4 + 255) / 256, 256>>>(song_x, songHi, songLo, NS * HF / 4);
    {
        dim3 g((HF * 256 + 255) / 256, 4);
        prep_weights<<<g, 256>>>(Wl1_sp, Wr1_sp, Wl1_ps, Wr1_ps, Wl2_sp, Wr2_sp, Wl2_ps, Wr2_ps, WHi, WLo);
    }

    const int aggBlkP = (NP + 7) / 8;
    const int aggBlkS = (NS + 7) / 8;
    const int tileP = (NP + 127) / 128;
    const int tileS = (NS + 127) / 128;
    const size_t WSZ = (size_t)HF * 256;

    // ---- layer 1 ----
    csr_agg<<<aggBlkP, 256>>>(song_x, offP, adjP, invP, aggPHi, aggPLo, NP);
    mma_dual_gemm<<<tileP, 256, GEMM_SMEM>>>(aggPHi, aggPLo, playHi, playLo,
                                             WHi + 0 * WSZ, WLo + 0 * WSZ, b1_sp,
                                             p1, p1Hi, p1Lo, NP, 1);
    csr_agg<<<aggBlkS, 256>>>(xplay, offS, adjS, invS, aggSHi, aggSLo, NS);
    mma_dual_gemm<<<tileS, 256, GEMM_SMEM>>>(aggSHi, aggSLo, songHi, songLo,
                                             WHi + 1 * WSZ, WLo + 1 * WSZ, b1_ps,
                                             s1, s1Hi, s1Lo, NS, 1);

    // ---- layer 2 ----
    csr_agg<<<aggBlkP, 256>>>(s1, offP, adjP, invP, aggPHi, aggPLo, NP);
    mma_dual_gemm<<<tileP, 256, GEMM_SMEM>>>(aggPHi, aggPLo, p1Hi, p1Lo,
                                             WHi + 2 * WSZ, WLo + 2 * WSZ, b2_sp,
                                             out_p2, ((__nv_bfloat16*)0), ((__nv_bfloat16*)0), NP, 0);
    csr_agg<<<aggBlkS, 256>>>(p1, offS, adjS, invS, aggSHi, aggSLo, NS);
    mma_dual_gemm<<<tileS, 256, GEMM_SMEM>>>(aggSHi, aggSLo, s1Hi, s1Lo,
                                             WHi + 3 * WSZ, WLo + 3 * WSZ, b2_ps,
                                             out_s2, ((__nv_bfloat16*)0), ((__nv_bfloat16*)0), NS, 0);
}

// round 7
// speedup vs baseline: 1.6082x; 1.0592x over previous
#include <cuda_runtime.h>
#include <cuda_bf16.h>
#include <cstdint>

#define NS_MAX 100000
#define NP_MAX 20000
#define E_MAX  500000
#define HF 128

// ======================= device scratch (no allocation allowed) ==============
__device__ float g_xplay[NP_MAX * HF];
__device__ float g_p1   [NP_MAX * HF];
__device__ float g_s1   [NS_MAX * HF];

__device__ __nv_bfloat16 g_songHi[NS_MAX * HF], g_songLo[NS_MAX * HF];
__device__ __nv_bfloat16 g_playHi[NP_MAX * HF], g_playLo[NP_MAX * HF];
__device__ __nv_bfloat16 g_aggPHi[NP_MAX * HF], g_aggPLo[NP_MAX * HF];
__device__ __nv_bfloat16 g_aggSHi[NS_MAX * HF], g_aggSLo[NS_MAX * HF];
__device__ __nv_bfloat16 g_p1Hi  [NP_MAX * HF], g_p1Lo  [NP_MAX * HF];
__device__ __nv_bfloat16 g_s1Hi  [NS_MAX * HF], g_s1Lo  [NS_MAX * HF];
__device__ __nv_bfloat16 g_WHi[4][HF * 256], g_WLo[4][HF * 256];  // B[n][k], k = concat(Wl,Wr)

__device__ int   g_cntP[NP_MAX], g_cntS[NS_MAX];
__device__ int   g_offP[NP_MAX + 1], g_offS[NS_MAX + 1];
__device__ int   g_curP[NP_MAX], g_curS[NS_MAX];
__device__ float g_invP[NP_MAX], g_invS[NS_MAX];
__device__ int   g_adjP[E_MAX], g_adjS[E_MAX];

// ======================= helpers =============================================
__device__ __forceinline__ uint32_t smem_u32(const void* p) {
    uint32_t a;
    asm("{ .reg .u64 t; cvta.to.shared.u64 t, %1; cvt.u32.u64 %0, t; }" : "=r"(a) : "l"(p));
    return a;
}
__device__ __forceinline__ uint32_t pack2bf(__nv_bfloat16 a, __nv_bfloat16 b) {
    return (uint32_t)__bfloat16_as_ushort(a) | ((uint32_t)__bfloat16_as_ushort(b) << 16);
}
__device__ __forceinline__ void split_f32(float x, __nv_bfloat16& h, __nv_bfloat16& l) {
    h = __float2bfloat16(x);
    l = __float2bfloat16(x - __bfloat162float(h));
}
__device__ __forceinline__ void ldsm_x4(uint32_t* r, uint32_t addr) {
    asm volatile("ldmatrix.sync.aligned.m8n8.x4.shared.b16 {%0,%1,%2,%3}, [%4];"
                 : "=r"(r[0]), "=r"(r[1]), "=r"(r[2]), "=r"(r[3]) : "r"(addr));
}
__device__ __forceinline__ void mma_bf16(float* d, const uint32_t* a, const uint32_t* b) {
    asm volatile("mma.sync.aligned.m16n8k16.row.col.f32.bf16.bf16.f32 "
                 "{%0,%1,%2,%3}, {%4,%5,%6,%7}, {%8,%9}, {%0,%1,%2,%3};"
                 : "+f"(d[0]), "+f"(d[1]), "+f"(d[2]), "+f"(d[3])
                 : "r"(a[0]), "r"(a[1]), "r"(a[2]), "r"(a[3]), "r"(b[0]), "r"(b[1]));
}

// ======================= graph-structure build ===============================
// launch 0: zero both degree arrays
__global__ void zero_cnt(int* __restrict__ cntP, int nP, int* __restrict__ cntS, int nS) {
    int i = blockIdx.x * blockDim.x + threadIdx.x;
    if (i < nP) cntP[i] = 0;
    if (i < nS) cntS[i] = 0;
    else if (i - nP < nS && i >= nP && i >= nS) {}   // (cntS covered by i<nS since nS>nP)
}

// launch 1
__global__ void count_kernel(const int* __restrict__ es, const int* __restrict__ ep,
                             int* __restrict__ cntS, int* __restrict__ cntP, int E) {
    int i = blockIdx.x * blockDim.x + threadIdx.x;
    if (i >= E) return;
    atomicAdd(&cntS[es[i]], 1);
    atomicAdd(&cntP[ep[i]], 1);
}

__device__ void scan_block(const int* __restrict__ cnt, int* __restrict__ off, int n) {
    __shared__ int wsum[32];
    __shared__ int carry;
    const int tid = threadIdx.x, lane = tid & 31, wid = tid >> 5;
    if (tid == 0) { carry = 0; off[0] = 0; }
    __syncthreads();
    const int CH = 4, step = blockDim.x * CH;
    for (int base = 0; base < n; base += step) {
        int i0 = base + tid * CH;
        int v[CH];
        #pragma unroll
        for (int k = 0; k < CH; k++) v[k] = (i0 + k < n) ? cnt[i0 + k] : 0;
        int t = v[0] + v[1] + v[2] + v[3];
        int x = t;
        #pragma unroll
        for (int d = 1; d < 32; d <<= 1) { int y = __shfl_up_sync(~0u, x, d); if (lane >= d) x += y; }
        if (lane == 31) wsum[wid] = x;
        __syncthreads();
        if (wid == 0) {
            int ws = (lane < (int)(blockDim.x >> 5)) ? wsum[lane] : 0;
            #pragma unroll
            for (int d = 1; d < 32; d <<= 1) { int y = __shfl_up_sync(~0u, ws, d); if (lane >= d) ws += y; }
            wsum[lane] = ws;
        }
        __syncthreads();
        int incl = x + (wid > 0 ? wsum[wid - 1] : 0) + carry;
        int run = incl - t;
        #pragma unroll
        for (int k = 0; k < CH; k++) { run += v[k]; if (i0 + k < n) off[i0 + k + 1] = run; }
        __syncthreads();
        if (tid == blockDim.x - 1) carry = incl;
        __syncthreads();
    }
}

// launch 2: blocks 0/1 scan + inv; blocks >=2 zero the cursor arrays
__global__ void scan_inv_zero(const int* cntP, int* offP, float* invP, int nP,
                              const int* cntS, int* offS, float* invS, int nS,
                              int* curP, int* curS) {
    if (blockIdx.x == 0) {
        scan_block(cntP, offP, nP);
        for (int i = threadIdx.x; i < nP; i += blockDim.x) invP[i] = 1.0f / (float)max(cntP[i], 1);
    } else if (blockIdx.x == 1) {
        scan_block(cntS, offS, nS);
        for (int i = threadIdx.x; i < nS; i += blockDim.x) invS[i] = 1.0f / (float)max(cntS[i], 1);
    } else {
        int t = (blockIdx.x - 2) * blockDim.x + threadIdx.x;
        if (t < nP) curP[t] = 0;
        else if (t - nP < nS) curS[t - nP] = 0;
    }
}

// launch 3
__global__ void fill_kernel(const int* __restrict__ es, const int* __restrict__ ep,
                            const int* __restrict__ offS, const int* __restrict__ offP,
                            int* __restrict__ curS, int* __restrict__ curP,
                            int* __restrict__ adjS, int* __restrict__ adjP, int E) {
    int i = blockIdx.x * blockDim.x + threadIdx.x;
    if (i >= E) return;
    int s = es[i], p = ep[i];
    int ps = atomicAdd(&curS[s], 1); adjS[offS[s] + ps] = p;
    int pp = atomicAdd(&curP[p], 1); adjP[offP[p] + pp] = s;
}

// ======================= launch 4: all conversions fused =====================
// block ranges: [0,Bg) gather_play, [Bg,Bg+Bc) convert song_x, [Bg+Bc,...) weights
__global__ void convert_all(const float* __restrict__ pe, const int* __restrict__ pid, int NP,
                            float* __restrict__ xplayF,
                            __nv_bfloat16* __restrict__ playHi, __nv_bfloat16* __restrict__ playLo,
                            const float* __restrict__ song, int NS,
                            __nv_bfloat16* __restrict__ songHi, __nv_bfloat16* __restrict__ songLo,
                            const float* Wl0, const float* Wr0, const float* Wl1, const float* Wr1,
                            const float* Wl2, const float* Wr2, const float* Wl3, const float* Wr3,
                            __nv_bfloat16* __restrict__ WHi, __nv_bfloat16* __restrict__ WLo,
                            int Bg, int Bc) {
    int b = blockIdx.x;
    if (b < Bg) {
        int t = b * blockDim.x + threadIdx.x;
        int row = t >> 5, lane = t & 31;
        if (row >= NP) return;
        float4 v = __ldg((const float4*)(pe + (size_t)pid[row] * HF) + lane);
        ((float4*)(xplayF + (size_t)row * HF))[lane] = v;
        __nv_bfloat16 h0,h1,h2,h3,l0,l1,l2,l3;
        split_f32(v.x,h0,l0); split_f32(v.y,h1,l1); split_f32(v.z,h2,l2); split_f32(v.w,h3,l3);
        ((uint2*)(playHi + (size_t)row * HF))[lane] = make_uint2(pack2bf(h0,h1), pack2bf(h2,h3));
        ((uint2*)(playLo + (size_t)row * HF))[lane] = make_uint2(pack2bf(l0,l1), pack2bf(l2,l3));
    } else if (b < Bg + Bc) {
        int i = (b - Bg) * blockDim.x + threadIdx.x;
        if (i >= NS * HF / 4) return;
        float4 v = __ldg((const float4*)song + i);
        __nv_bfloat16 h0,h1,h2,h3,l0,l1,l2,l3;
        split_f32(v.x,h0,l0); split_f32(v.y,h1,l1); split_f32(v.z,h2,l2); split_f32(v.w,h3,l3);
        ((uint2*)songHi)[i] = make_uint2(pack2bf(h0,h1), pack2bf(h2,h3));
        ((uint2*)songLo)[i] = make_uint2(pack2bf(l0,l1), pack2bf(l2,l3));
    } else {
        int lb = b - Bg - Bc;                    // 0..511
        int pair = lb >> 7;                      // 128 blocks per pair
        int idx = (lb & 127) * 256 + threadIdx.x;   // 0..32767
        const float* Wl = pair == 0 ? Wl0 : pair == 1 ? Wl1 : pair == 2 ? Wl2 : Wl3;
        const float* Wr = pair == 0 ? Wr0 : pair == 1 ? Wr1 : pair == 2 ? Wr2 : Wr3;
        int k = idx & 255, n = idx >> 8;
        float w = (k < 128) ? Wl[(size_t)k * HF + n] : Wr[(size_t)(k - 128) * HF + n];
        __nv_bfloat16 h, l; split_f32(w, h, l);
        WHi[(size_t)pair * HF * 256 + (size_t)n * 256 + k] = h;
        WLo[(size_t)pair * HF * 256 + (size_t)n * 256 + k] = l;
    }
}

// ======================= CSR mean-aggregation (fp32 in, bf16 hi/lo out) ======
__global__ void csr_agg(const float* __restrict__ src,
                        const int* __restrict__ off, const int* __restrict__ adj,
                        const float* __restrict__ inv,
                        __nv_bfloat16* __restrict__ outHi, __nv_bfloat16* __restrict__ outLo,
                        int Ndst) {
    int warp = (blockIdx.x * blockDim.x + threadIdx.x) >> 5;
    int lane = threadIdx.x & 31;
    if (warp >= Ndst) return;
    int s0 = off[warp], s1 = off[warp + 1];
    float4 acc = make_float4(0.f, 0.f, 0.f, 0.f);
    for (int e = s0; e < s1; e += 32) {
        int myE = e + lane;
        int myIdx = (myE < s1) ? __ldg(adj + myE) : 0;
        int cnt = min(32, s1 - e);
        for (int j = 0; j < cnt; j++) {
            int sidx = __shfl_sync(~0u, myIdx, j);
            float4 v = __ldg(((const float4*)src) + (size_t)sidx * 32 + lane);
            acc.x += v.x; acc.y += v.y; acc.z += v.z; acc.w += v.w;
        }
    }
    float w = inv[warp];
    acc.x *= w; acc.y *= w; acc.z *= w; acc.w *= w;
    __nv_bfloat16 h0,h1,h2,h3,l0,l1,l2,l3;
    split_f32(acc.x,h0,l0); split_f32(acc.y,h1,l1); split_f32(acc.z,h2,l2); split_f32(acc.w,h3,l3);
    ((uint2*)(outHi + (size_t)warp * HF))[lane] = make_uint2(pack2bf(h0,h1), pack2bf(h2,h3));
    ((uint2*)(outLo + (size_t)warp * HF))[lane] = make_uint2(pack2bf(l0,l1), pack2bf(l2,l3));
}

// ======================= mma.sync split-bf16 dual GEMM =======================
// out = act(A1 @ Wl + b + A2 @ Wr).  Block tile 128x128, K-concat 256 in 4
// chunks of 64.  Per ks: fragments loaded ONCE (Ah, Al, Bh), passes Ah*Bh and
// Al*Bh from regs, then Bl overwrite + pass Ah*Bl.  12 LDSM / 48 MMA per ks.
#define GEMM_SMEM 65536
#define OFF_AH 0
#define OFF_AL 16384
#define OFF_BH 32768
#define OFF_BL 49152

__device__ __forceinline__ int sw_off(int r, int q) {      // r: row 0..127, q: 16B group 0..7
    return r * 128 + ((q ^ (r & 7)) << 4);
}

__global__ __launch_bounds__(256, 2)
void mma_dual_gemm(const __nv_bfloat16* __restrict__ A1Hi, const __nv_bfloat16* __restrict__ A1Lo,
                   const __nv_bfloat16* __restrict__ A2Hi, const __nv_bfloat16* __restrict__ A2Lo,
                   const __nv_bfloat16* __restrict__ BHi,  const __nv_bfloat16* __restrict__ BLo,
                   const float* __restrict__ bias,
                   float* __restrict__ outF,
                   __nv_bfloat16* __restrict__ outHi, __nv_bfloat16* __restrict__ outLo,
                   int N, int doRelu) {
    extern __shared__ char smem[];
    const uint32_t sb = smem_u32(smem);
    const int tid = threadIdx.x, wid = tid >> 5, lane = tid & 31;
    const int rowBase = blockIdx.x * 128;

    // warp tiling: 4 warps along M (32 rows each), 2 along N (64 cols each)
    const int mBase = (wid & 3) * 32;
    const int nBase = (wid >> 2) * 64;

    float acc[2][8][4];
    #pragma unroll
    for (int mt = 0; mt < 2; mt++)
        #pragma unroll
        for (int nt = 0; nt < 8; nt++)
            #pragma unroll
            for (int j = 0; j < 4; j++) acc[mt][nt][j] = 0.f;

    // per-lane ldmatrix address components
    const int rowA  = mBase + (lane & 15);                 // + mt*16
    const int partA = lane >> 4;
    const int swA   = rowA & 7;
    const int rowB  = nBase + ((lane >> 4) << 3) + (lane & 7);   // + p*16
    const int partB = (lane >> 3) & 1;
    const int swB   = rowB & 7;                            // p*16 preserves &7

    #pragma unroll 1
    for (int c = 0; c < 4; c++) {
        const __nv_bfloat16* AH = (c < 2) ? A1Hi : A2Hi;
        const __nv_bfloat16* AL = (c < 2) ? A1Lo : A2Lo;
        const int kA = (c & 1) * 64;
        const int kB = c * 64;

        __syncthreads();   // previous chunk's compute done -> smem reusable
        #pragma unroll
        for (int u = 0; u < 4; u++) {
            int idx = tid + u * 256;
            int r = idx >> 3, q = idx & 7;
            int gr = rowBase + r;
            uint4 vah, val;
            if (gr < N) {
                vah = __ldg((const uint4*)(AH + (size_t)gr * HF + kA) + q);
                val = __ldg((const uint4*)(AL + (size_t)gr * HF + kA) + q);
            } else { vah = make_uint4(0,0,0,0); val = vah; }
            uint4 vbh = __ldg((const uint4*)(BHi + (size_t)r * 256 + kB) + q);
            uint4 vbl = __ldg((const uint4*)(BLo + (size_t)r * 256 + kB) + q);
            int so = sw_off(r, q);
            *(uint4*)(smem + OFF_AH + so) = vah;
            *(uint4*)(smem + OFF_AL + so) = val;
            *(uint4*)(smem + OFF_BH + so) = vbh;
            *(uint4*)(smem + OFF_BL + so) = vbl;
        }
        __syncthreads();

        #pragma unroll
        for (int ks = 0; ks < 4; ks++) {
            uint32_t ah[2][4], al[2][4], b[8][2];
            const int qa = ((ks * 2 + partA) ^ swA) << 4;
            const int qb = ((ks * 2 + partB) ^ swB) << 4;
            #pragma unroll
            for (int mt = 0; mt < 2; mt++) {
                ldsm_x4(ah[mt], sb + OFF_AH + (rowA + mt * 16) * 128 + qa);
                ldsm_x4(al[mt], sb + OFF_AL + (rowA + mt * 16) * 128 + qa);
            }
            #pragma unroll
            for (int p = 0; p < 4; p++)
                ldsm_x4(&b[p * 2][0], sb + OFF_BH + (rowB + p * 16) * 128 + qb);
            #pragma unroll
            for (int mt = 0; mt < 2; mt++)
                #pragma unroll
                for (int nt = 0; nt < 8; nt++)
                    mma_bf16(acc[mt][nt], ah[mt], b[nt]);
            #pragma unroll
            for (int mt = 0; mt < 2; mt++)
                #pragma unroll
                for (int nt = 0; nt < 8; nt++)
                    mma_bf16(acc[mt][nt], al[mt], b[nt]);
            #pragma unroll
            for (int p = 0; p < 4; p++)
                ldsm_x4(&b[p * 2][0], sb + OFF_BL + (rowB + p * 16) * 128 + qb);
            #pragma unroll
            for (int mt = 0; mt < 2; mt++)
                #pragma unroll
                for (int nt = 0; nt < 8; nt++)
                    mma_bf16(acc[mt][nt], ah[mt], b[nt]);
        }
    }

    // ---- epilogue: bias (+relu), fp32 store, optional bf16 hi/lo split ------
    const int erow = lane >> 2;               // 0..7
    const int ecol = (lane & 3) * 2;          // 0,2,4,6
    #pragma unroll
    for (int mt = 0; mt < 2; mt++) {
        #pragma unroll
        for (int nt = 0; nt < 8; nt++) {
            int col = nBase + nt * 8 + ecol;
            float2 bb = *(const float2*)(bias + col);
            #pragma unroll
            for (int h = 0; h < 2; h++) {     // h=0: rows r, h=1: rows r+8
                int gr = rowBase + mBase + mt * 16 + erow + h * 8;
                if (gr < N) {
                    float x0 = acc[mt][nt][h * 2 + 0] + bb.x;
                    float x1 = acc[mt][nt][h * 2 + 1] + bb.y;
                    if (doRelu) { x0 = fmaxf(x0, 0.f); x1 = fmaxf(x1, 0.f); }
                    *(float2*)(outF + (size_t)gr * HF + col) = make_float2(x0, x1);
                    if (outHi) {
                        __nv_bfloat16 h0, h1, l0, l1;
                        split_f32(x0, h0, l0); split_f32(x1, h1, l1);
                        *(uint32_t*)(outHi + (size_t)gr * HF + col) = pack2bf(h0, h1);
                        *(uint32_t*)(outLo + (size_t)gr * HF + col) = pack2bf(l0, l1);
                    }
                }
            }
        }
    }
}

// ======================= launch =============================================
extern "C" void kernel_launch(void* const* d_in, const int* in_sizes, int n_in,
                              void* d_out, int out_size) {
    const float* song_x = (const float*)d_in[0];
    const int*   pid    = (const int*)  d_in[1];
    const int*   es     = (const int*)  d_in[2];
    const int*   ep     = (const int*)  d_in[3];
    const float* pemb   = (const float*)d_in[4];
    const float* Wl1_sp = (const float*)d_in[5];
    const float* Wr1_sp = (const float*)d_in[6];
    const float* b1_sp  = (const float*)d_in[7];
    const float* Wl1_ps = (const float*)d_in[8];
    const float* Wr1_ps = (const float*)d_in[9];
    const float* b1_ps  = (const float*)d_in[10];
    const float* Wl2_sp = (const float*)d_in[11];
    const float* Wr2_sp = (const float*)d_in[12];
    const float* b2_sp  = (const float*)d_in[13];
    const float* Wl2_ps = (const float*)d_in[14];
    const float* Wr2_ps = (const float*)d_in[15];
    const float* b2_ps  = (const float*)d_in[16];

    const int NS = in_sizes[0] / HF;
    const int NP = in_sizes[1];
    const int E  = in_sizes[2];

    float *xplay, *p1, *s1, *invP, *invS;
    int *cntP, *cntS, *offP, *offS, *curP, *curS, *adjP, *adjS;
    __nv_bfloat16 *songHi,*songLo,*playHi,*playLo,*aggPHi,*aggPLo,*aggSHi,*aggSLo,*p1Hi,*p1Lo,*s1Hi,*s1Lo,*WHi,*WLo;
    cudaGetSymbolAddress((void**)&xplay, g_xplay);
    cudaGetSymbolAddress((void**)&p1,    g_p1);
    cudaGetSymbolAddress((void**)&s1,    g_s1);
    cudaGetSymbolAddress((void**)&invP,  g_invP);
    cudaGetSymbolAddress((void**)&invS,  g_invS);
    cudaGetSymbolAddress((void**)&cntP,  g_cntP);
    cudaGetSymbolAddress((void**)&cntS,  g_cntS);
    cudaGetSymbolAddress((void**)&offP,  g_offP);
    cudaGetSymbolAddress((void**)&offS,  g_offS);
    cudaGetSymbolAddress((void**)&curP,  g_curP);
    cudaGetSymbolAddress((void**)&curS,  g_curS);
    cudaGetSymbolAddress((void**)&adjP,  g_adjP);
    cudaGetSymbolAddress((void**)&adjS,  g_adjS);
    cudaGetSymbolAddress((void**)&songHi, g_songHi); cudaGetSymbolAddress((void**)&songLo, g_songLo);
    cudaGetSymbolAddress((void**)&playHi, g_playHi); cudaGetSymbolAddress((void**)&playLo, g_playLo);
    cudaGetSymbolAddress((void**)&aggPHi, g_aggPHi); cudaGetSymbolAddress((void**)&aggPLo, g_aggPLo);
    cudaGetSymbolAddress((void**)&aggSHi, g_aggSHi); cudaGetSymbolAddress((void**)&aggSLo, g_aggSLo);
    cudaGetSymbolAddress((void**)&p1Hi,   g_p1Hi);   cudaGetSymbolAddress((void**)&p1Lo,   g_p1Lo);
    cudaGetSymbolAddress((void**)&s1Hi,   g_s1Hi);   cudaGetSymbolAddress((void**)&s1Lo,   g_s1Lo);
    cudaGetSymbolAddress((void**)&WHi,    g_WHi);    cudaGetSymbolAddress((void**)&WLo,    g_WLo);

    float* out_s2 = (float*)d_out;
    float* out_p2 = (float*)d_out + (size_t)NS * HF;

    static int smem_set = 0;
    if (!smem_set) {
        cudaFuncSetAttribute(mma_dual_gemm, cudaFuncAttributeMaxDynamicSharedMemorySize, GEMM_SMEM);
        smem_set = 1;
    }

    // launch 0: zero degree arrays
    zero_cnt<<<(max(NS, NP) + 255) / 256, 256>>>(cntP, NP, cntS, NS);
    // launch 1: degree histogram
    count_kernel<<<(E + 255) / 256, 256>>>(es, ep, cntS, cntP, E);
    // launch 2: scan + inverse-degree + cursor zero
    scan_inv_zero<<<2 + (NP + NS + 1023) / 1024, 1024>>>(cntP, offP, invP, NP,
                                                          cntS, offS, invS, NS, curP, curS);
    // launch 3: CSR fill
    fill_kernel<<<(E + 255) / 256, 256>>>(es, ep, offS, offP, curS, curP, adjS, adjP, E);
    // launch 4: all conversions fused
    {
        int Bg = (NP * 32 + 255) / 256;
        int Bc = (NS * HF / 4 + 255) / 256;
        convert_all<<<Bg + Bc + 512, 256>>>(pemb, pid, NP, xplay, playHi, playLo,
                                            song_x, NS, songHi, songLo,
                                            Wl1_sp, Wr1_sp, Wl1_ps, Wr1_ps,
                                            Wl2_sp, Wr2_sp, Wl2_ps, Wr2_ps,
                                            WHi, WLo, Bg, Bc);
    }

    const int aggBlkP = (NP + 7) / 8;
    const int aggBlkS = (NS + 7) / 8;
    const int tileP = (NP + 127) / 128;
    const int tileS = (NS + 127) / 128;
    const size_t WSZ = (size_t)HF * 256;

    // launch 5 (profiled): S-side aggregation, layer 1
    csr_agg<<<aggBlkS, 256>>>(xplay, offS, adjS, invS, aggSHi, aggSLo, NS);
    // launch 6: s1 = relu(aggS @ Wl1_ps + b + song @ Wr1_ps)
    mma_dual_gemm<<<tileS, 256, GEMM_SMEM>>>(aggSHi, aggSLo, songHi, songLo,
                                             WHi + 1 * WSZ, WLo + 1 * WSZ, b1_ps,
                                             s1, s1Hi, s1Lo, NS, 1);
    // launch 7/8: P-side layer 1
    csr_agg<<<aggBlkP, 256>>>(song_x, offP, adjP, invP, aggPHi, aggPLo, NP);
    mma_dual_gemm<<<tileP, 256, GEMM_SMEM>>>(aggPHi, aggPLo, playHi, playLo,
                                             WHi + 0 * WSZ, WLo + 0 * WSZ, b1_sp,
                                             p1, p1Hi, p1Lo, NP, 1);
    // launch 9/10: P-side layer 2
    csr_agg<<<aggBlkP, 256>>>(s1, offP, adjP, invP, aggPHi, aggPLo, NP);
    mma_dual_gemm<<<tileP, 256, GEMM_SMEM>>>(aggPHi, aggPLo, p1Hi, p1Lo,
                                             WHi + 2 * WSZ, WLo + 2 * WSZ, b2_sp,
                                             out_p2, ((__nv_bfloat16*)0), ((__nv_bfloat16*)0), NP, 0);
    // launch 11/12: S-side layer 2
    csr_agg<<<aggBlkS, 256>>>(p1, offS, adjS, invS, aggSHi, aggSLo, NS);
    mma_dual_gemm<<<tileS, 256, GEMM_SMEM>>>(aggSHi, aggSLo, s1Hi, s1Lo,
                                             WHi + 3 * WSZ, WLo + 3 * WSZ, b2_ps,
                                             out_s2, ((__nv_bfloat16*)0), ((__nv_bfloat16*)0), NS, 0);
}

// round 8
// speedup vs baseline: 1.7686x; 1.0998x over previous
#include <cuda_runtime.h>
#include <cuda_bf16.h>
#include <cstdint>

#define NS_MAX 100000
#define NP_MAX 20000
#define E_MAX  500000
#define HF 128

// ======================= device scratch (no allocation allowed) ==============
__device__ float g_xplay[NP_MAX * HF];
__device__ float g_p1   [NP_MAX * HF];
__device__ float g_s1   [NS_MAX * HF];

__device__ __nv_bfloat16 g_songHi[NS_MAX * HF], g_songLo[NS_MAX * HF];
__device__ __nv_bfloat16 g_playHi[NP_MAX * HF], g_playLo[NP_MAX * HF];
__device__ __nv_bfloat16 g_aggPHi[NP_MAX * HF], g_aggPLo[NP_MAX * HF];
__device__ __nv_bfloat16 g_aggSHi[NS_MAX * HF], g_aggSLo[NS_MAX * HF];
__device__ __nv_bfloat16 g_p1Hi  [NP_MAX * HF], g_p1Lo  [NP_MAX * HF];
__device__ __nv_bfloat16 g_s1Hi  [NS_MAX * HF], g_s1Lo  [NS_MAX * HF];
__device__ __nv_bfloat16 g_WHi[4][HF * 256], g_WLo[4][HF * 256];  // B[n][k], k = concat(Wl,Wr)

__device__ int   g_cntP[NP_MAX], g_cntS[NS_MAX];
__device__ int   g_offP[NP_MAX + 1], g_offS[NS_MAX + 1];
__device__ int   g_curP[NP_MAX], g_curS[NS_MAX];
__device__ float g_invP[NP_MAX], g_invS[NS_MAX];
__device__ int   g_adjP[E_MAX], g_adjS[E_MAX];

// ======================= helpers =============================================
__device__ __forceinline__ uint32_t smem_u32(const void* p) {
    uint32_t a;
    asm("{ .reg .u64 t; cvta.to.shared.u64 t, %1; cvt.u32.u64 %0, t; }" : "=r"(a) : "l"(p));
    return a;
}
__device__ __forceinline__ uint32_t pack2bf(__nv_bfloat16 a, __nv_bfloat16 b) {
    return (uint32_t)__bfloat16_as_ushort(a) | ((uint32_t)__bfloat16_as_ushort(b) << 16);
}
__device__ __forceinline__ void split_f32(float x, __nv_bfloat16& h, __nv_bfloat16& l) {
    h = __float2bfloat16(x);
    l = __float2bfloat16(x - __bfloat162float(h));
}
__device__ __forceinline__ void ldsm_x4(uint32_t* r, uint32_t addr) {
    asm volatile("ldmatrix.sync.aligned.m8n8.x4.shared.b16 {%0,%1,%2,%3}, [%4];"
                 : "=r"(r[0]), "=r"(r[1]), "=r"(r[2]), "=r"(r[3]) : "r"(addr));
}
__device__ __forceinline__ void mma_bf16(float* d, const uint32_t* a, const uint32_t* b) {
    asm volatile("mma.sync.aligned.m16n8k16.row.col.f32.bf16.bf16.f32 "
                 "{%0,%1,%2,%3}, {%4,%5,%6,%7}, {%8,%9}, {%0,%1,%2,%3};"
                 : "+f"(d[0]), "+f"(d[1]), "+f"(d[2]), "+f"(d[3])
                 : "r"(a[0]), "r"(a[1]), "r"(a[2]), "r"(a[3]), "r"(b[0]), "r"(b[1]));
}

// ======================= graph-structure build ===============================
__global__ void zero_cnt(int* __restrict__ cntP, int nP, int* __restrict__ cntS, int nS) {
    int i = blockIdx.x * blockDim.x + threadIdx.x;
    if (i < nP) cntP[i] = 0;
    if (i < nS) cntS[i] = 0;
}

__global__ void count_kernel(const int* __restrict__ es, const int* __restrict__ ep,
                             int* __restrict__ cntS, int* __restrict__ cntP, int E) {
    int i = blockIdx.x * blockDim.x + threadIdx.x;
    if (i >= E) return;
    atomicAdd(&cntS[es[i]], 1);
    atomicAdd(&cntP[ep[i]], 1);
}

__device__ void scan_block(const int* __restrict__ cnt, int* __restrict__ off, int n) {
    __shared__ int wsum[32];
    __shared__ int carry;
    const int tid = threadIdx.x, lane = tid & 31, wid = tid >> 5;
    if (tid == 0) { carry = 0; off[0] = 0; }
    __syncthreads();
    const int CH = 4, step = blockDim.x * CH;
    for (int base = 0; base < n; base += step) {
        int i0 = base + tid * CH;
        int v[CH];
        #pragma unroll
        for (int k = 0; k < CH; k++) v[k] = (i0 + k < n) ? cnt[i0 + k] : 0;
        int t = v[0] + v[1] + v[2] + v[3];
        int x = t;
        #pragma unroll
        for (int d = 1; d < 32; d <<= 1) { int y = __shfl_up_sync(~0u, x, d); if (lane >= d) x += y; }
        if (lane == 31) wsum[wid] = x;
        __syncthreads();
        if (wid == 0) {
            int ws = (lane < (int)(blockDim.x >> 5)) ? wsum[lane] : 0;
            #pragma unroll
            for (int d = 1; d < 32; d <<= 1) { int y = __shfl_up_sync(~0u, ws, d); if (lane >= d) ws += y; }
            wsum[lane] = ws;
        }
        __syncthreads();
        int incl = x + (wid > 0 ? wsum[wid - 1] : 0) + carry;
        int run = incl - t;
        #pragma unroll
        for (int k = 0; k < CH; k++) { run += v[k]; if (i0 + k < n) off[i0 + k + 1] = run; }
        __syncthreads();
        if (tid == blockDim.x - 1) carry = incl;
        __syncthreads();
    }
}

__global__ void scan_inv_zero(const int* cntP, int* offP, float* invP, int nP,
                              const int* cntS, int* offS, float* invS, int nS,
                              int* curP, int* curS) {
    if (blockIdx.x == 0) {
        scan_block(cntP, offP, nP);
        for (int i = threadIdx.x; i < nP; i += blockDim.x) invP[i] = 1.0f / (float)max(cntP[i], 1);
    } else if (blockIdx.x == 1) {
        scan_block(cntS, offS, nS);
        for (int i = threadIdx.x; i < nS; i += blockDim.x) invS[i] = 1.0f / (float)max(cntS[i], 1);
    } else {
        int t = (blockIdx.x - 2) * blockDim.x + threadIdx.x;
        if (t < nP) curP[t] = 0;
        else if (t - nP < nS) curS[t - nP] = 0;
    }
}

__global__ void fill_kernel(const int* __restrict__ es, const int* __restrict__ ep,
                            const int* __restrict__ offS, const int* __restrict__ offP,
                            int* __restrict__ curS, int* __restrict__ curP,
                            int* __restrict__ adjS, int* __restrict__ adjP, int E) {
    int i = blockIdx.x * blockDim.x + threadIdx.x;
    if (i >= E) return;
    int s = es[i], p = ep[i];
    int ps = atomicAdd(&curS[s], 1); adjS[offS[s] + ps] = p;
    int pp = atomicAdd(&curP[p], 1); adjP[offP[p] + pp] = s;
}

// ======================= all conversions fused ===============================
__global__ void convert_all(const float* __restrict__ pe, const int* __restrict__ pid, int NP,
                            float* __restrict__ xplayF,
                            __nv_bfloat16* __restrict__ playHi, __nv_bfloat16* __restrict__ playLo,
                            const float* __restrict__ song, int NS,
                            __nv_bfloat16* __restrict__ songHi, __nv_bfloat16* __restrict__ songLo,
                            const float* Wl0, const float* Wr0, const float* Wl1, const float* Wr1,
                            const float* Wl2, const float* Wr2, const float* Wl3, const float* Wr3,
                            __nv_bfloat16* __restrict__ WHi, __nv_bfloat16* __restrict__ WLo,
                            int Bg, int Bc) {
    int b = blockIdx.x;
    if (b < Bg) {
        int t = b * blockDim.x + threadIdx.x;
        int row = t >> 5, lane = t & 31;
        if (row >= NP) return;
        float4 v = __ldg((const float4*)(pe + (size_t)pid[row] * HF) + lane);
        ((float4*)(xplayF + (size_t)row * HF))[lane] = v;
        __nv_bfloat16 h0,h1,h2,h3,l0,l1,l2,l3;
        split_f32(v.x,h0,l0); split_f32(v.y,h1,l1); split_f32(v.z,h2,l2); split_f32(v.w,h3,l3);
        ((uint2*)(playHi + (size_t)row * HF))[lane] = make_uint2(pack2bf(h0,h1), pack2bf(h2,h3));
        ((uint2*)(playLo + (size_t)row * HF))[lane] = make_uint2(pack2bf(l0,l1), pack2bf(l2,l3));
    } else if (b < Bg + Bc) {
        int i = (b - Bg) * blockDim.x + threadIdx.x;
        if (i >= NS * HF / 4) return;
        float4 v = __ldg((const float4*)song + i);
        __nv_bfloat16 h0,h1,h2,h3,l0,l1,l2,l3;
        split_f32(v.x,h0,l0); split_f32(v.y,h1,l1); split_f32(v.z,h2,l2); split_f32(v.w,h3,l3);
        ((uint2*)songHi)[i] = make_uint2(pack2bf(h0,h1), pack2bf(h2,h3));
        ((uint2*)songLo)[i] = make_uint2(pack2bf(l0,l1), pack2bf(l2,l3));
    } else {
        int lb = b - Bg - Bc;                    // 0..511
        int pair = lb >> 7;
        int idx = (lb & 127) * 256 + threadIdx.x;
        const float* Wl = pair == 0 ? Wl0 : pair == 1 ? Wl1 : pair == 2 ? Wl2 : Wl3;
        const float* Wr = pair == 0 ? Wr0 : pair == 1 ? Wr1 : pair == 2 ? Wr2 : Wr3;
        int k = idx & 255, n = idx >> 8;
        float w = (k < 128) ? Wl[(size_t)k * HF + n] : Wr[(size_t)(k - 128) * HF + n];
        __nv_bfloat16 h, l; split_f32(w, h, l);
        WHi[(size_t)pair * HF * 256 + (size_t)n * 256 + k] = h;
        WLo[(size_t)pair * HF * 256 + (size_t)n * 256 + k] = l;
    }
}

// ======================= CSR mean-aggregation (fp32 in, bf16 hi/lo out) ======
__global__ void csr_agg(const float* __restrict__ src,
                        const int* __restrict__ off, const int* __restrict__ adj,
                        const float* __restrict__ inv,
                        __nv_bfloat16* __restrict__ outHi, __nv_bfloat16* __restrict__ outLo,
                        int Ndst) {
    int warp = (blockIdx.x * blockDim.x + threadIdx.x) >> 5;
    int lane = threadIdx.x & 31;
    if (warp >= Ndst) return;
    int s0 = off[warp], s1 = off[warp + 1];
    float4 acc = make_float4(0.f, 0.f, 0.f, 0.f);
    for (int e = s0; e < s1; e += 32) {
        int myE = e + lane;
        int myIdx = (myE < s1) ? __ldg(adj + myE) : 0;
        int cnt = min(32, s1 - e);
        for (int j = 0; j < cnt; j++) {
            int sidx = __shfl_sync(~0u, myIdx, j);
            float4 v = __ldg(((const float4*)src) + (size_t)sidx * 32 + lane);
            acc.x += v.x; acc.y += v.y; acc.z += v.z; acc.w += v.w;
        }
    }
    float w = inv[warp];
    acc.x *= w; acc.y *= w; acc.z *= w; acc.w *= w;
    __nv_bfloat16 h0,h1,h2,h3,l0,l1,l2,l3;
    split_f32(acc.x,h0,l0); split_f32(acc.y,h1,l1); split_f32(acc.z,h2,l2); split_f32(acc.w,h3,l3);
    ((uint2*)(outHi + (size_t)warp * HF))[lane] = make_uint2(pack2bf(h0,h1), pack2bf(h2,h3));
    ((uint2*)(outLo + (size_t)warp * HF))[lane] = make_uint2(pack2bf(l0,l1), pack2bf(l2,l3));
}

// ======================= mma.sync split-bf16 dual GEMM =======================
#define GEMM_SMEM 65536
#define OFF_AH 0
#define OFF_AL 16384
#define OFF_BH 32768
#define OFF_BL 49152

__device__ __forceinline__ int sw_off(int r, int q) {
    return r * 128 + ((q ^ (r & 7)) << 4);
}

__global__ __launch_bounds__(256, 2)
void mma_dual_gemm(const __nv_bfloat16* __restrict__ A1Hi, const __nv_bfloat16* __restrict__ A1Lo,
                   const __nv_bfloat16* __restrict__ A2Hi, const __nv_bfloat16* __restrict__ A2Lo,
                   const __nv_bfloat16* __restrict__ BHi,  const __nv_bfloat16* __restrict__ BLo,
                   const float* __restrict__ bias,
                   float* __restrict__ outF,
                   __nv_bfloat16* __restrict__ outHi, __nv_bfloat16* __restrict__ outLo,
                   int N, int doRelu) {
    extern __shared__ char smem[];
    const uint32_t sb = smem_u32(smem);
    const int tid = threadIdx.x, wid = tid >> 5, lane = tid & 31;
    const int rowBase = blockIdx.x * 128;

    const int mBase = (wid & 3) * 32;
    const int nBase = (wid >> 2) * 64;

    float acc[2][8][4];
    #pragma unroll
    for (int mt = 0; mt < 2; mt++)
        #pragma unroll
        for (int nt = 0; nt < 8; nt++)
            #pragma unroll
            for (int j = 0; j < 4; j++) acc[mt][nt][j] = 0.f;

    const int rowA  = mBase + (lane & 15);
    const int partA = lane >> 4;
    const int swA   = rowA & 7;
    const int rowB  = nBase + ((lane >> 4) << 3) + (lane & 7);
    const int partB = (lane >> 3) & 1;
    const int swB   = rowB & 7;

    #pragma unroll 1
    for (int c = 0; c < 4; c++) {
        const __nv_bfloat16* AH = (c < 2) ? A1Hi : A2Hi;
        const __nv_bfloat16* AL = (c < 2) ? A1Lo : A2Lo;
        const int kA = (c & 1) * 64;
        const int kB = c * 64;

        __syncthreads();
        #pragma unroll
        for (int u = 0; u < 4; u++) {
            int idx = tid + u * 256;
            int r = idx >> 3, q = idx & 7;
            int gr = rowBase + r;
            uint4 vah, val;
            if (gr < N) {
                vah = __ldg((const uint4*)(AH + (size_t)gr * HF + kA) + q);
                val = __ldg((const uint4*)(AL + (size_t)gr * HF + kA) + q);
            } else { vah = make_uint4(0,0,0,0); val = vah; }
            uint4 vbh = __ldg((const uint4*)(BHi + (size_t)r * 256 + kB) + q);
            uint4 vbl = __ldg((const uint4*)(BLo + (size_t)r * 256 + kB) + q);
            int so = sw_off(r, q);
            *(uint4*)(smem + OFF_AH + so) = vah;
            *(uint4*)(smem + OFF_AL + so) = val;
            *(uint4*)(smem + OFF_BH + so) = vbh;
            *(uint4*)(smem + OFF_BL + so) = vbl;
        }
        __syncthreads();

        #pragma unroll
        for (int ks = 0; ks < 4; ks++) {
            uint32_t ah[2][4], al[2][4], b[8][2];
            const int qa = ((ks * 2 + partA) ^ swA) << 4;
            const int qb = ((ks * 2 + partB) ^ swB) << 4;
            #pragma unroll
            for (int mt = 0; mt < 2; mt++) {
                ldsm_x4(ah[mt], sb + OFF_AH + (rowA + mt * 16) * 128 + qa);
                ldsm_x4(al[mt], sb + OFF_AL + (rowA + mt * 16) * 128 + qa);
            }
            #pragma unroll
            for (int p = 0; p < 4; p++)
                ldsm_x4(&b[p * 2][0], sb + OFF_BH + (rowB + p * 16) * 128 + qb);
            #pragma unroll
            for (int mt = 0; mt < 2; mt++)
                #pragma unroll
                for (int nt = 0; nt < 8; nt++)
                    mma_bf16(acc[mt][nt], ah[mt], b[nt]);
            #pragma unroll
            for (int mt = 0; mt < 2; mt++)
                #pragma unroll
                for (int nt = 0; nt < 8; nt++)
                    mma_bf16(acc[mt][nt], al[mt], b[nt]);
            #pragma unroll
            for (int p = 0; p < 4; p++)
                ldsm_x4(&b[p * 2][0], sb + OFF_BL + (rowB + p * 16) * 128 + qb);
            #pragma unroll
            for (int mt = 0; mt < 2; mt++)
                #pragma unroll
                for (int nt = 0; nt < 8; nt++)
                    mma_bf16(acc[mt][nt], ah[mt], b[nt]);
        }
    }

    const int erow = lane >> 2;
    const int ecol = (lane & 3) * 2;
    #pragma unroll
    for (int mt = 0; mt < 2; mt++) {
        #pragma unroll
        for (int nt = 0; nt < 8; nt++) {
            int col = nBase + nt * 8 + ecol;
            float2 bb = *(const float2*)(bias + col);
            #pragma unroll
            for (int h = 0; h < 2; h++) {
                int gr = rowBase + mBase + mt * 16 + erow + h * 8;
                if (gr < N) {
                    float x0 = acc[mt][nt][h * 2 + 0] + bb.x;
                    float x1 = acc[mt][nt][h * 2 + 1] + bb.y;
                    if (doRelu) { x0 = fmaxf(x0, 0.f); x1 = fmaxf(x1, 0.f); }
                    *(float2*)(outF + (size_t)gr * HF + col) = make_float2(x0, x1);
                    if (outHi) {
                        __nv_bfloat16 h0, h1, l0, l1;
                        split_f32(x0, h0, l0); split_f32(x1, h1, l1);
                        *(uint32_t*)(outHi + (size_t)gr * HF + col) = pack2bf(h0, h1);
                        *(uint32_t*)(outLo + (size_t)gr * HF + col) = pack2bf(l0, l1);
                    }
                }
            }
        }
    }
}

// ======================= launch (fork-join multi-stream graph) ===============
extern "C" void kernel_launch(void* const* d_in, const int* in_sizes, int n_in,
                              void* d_out, int out_size) {
    const float* song_x = (const float*)d_in[0];
    const int*   pid    = (const int*)  d_in[1];
    const int*   es     = (const int*)  d_in[2];
    const int*   ep     = (const int*)  d_in[3];
    const float* pemb   = (const float*)d_in[4];
    const float* Wl1_sp = (const float*)d_in[5];
    const float* Wr1_sp = (const float*)d_in[6];
    const float* b1_sp  = (const float*)d_in[7];
    const float* Wl1_ps = (const float*)d_in[8];
    const float* Wr1_ps = (const float*)d_in[9];
    const float* b1_ps  = (const float*)d_in[10];
    const float* Wl2_sp = (const float*)d_in[11];
    const float* Wr2_sp = (const float*)d_in[12];
    const float* b2_sp  = (const float*)d_in[13];
    const float* Wl2_ps = (const float*)d_in[14];
    const float* Wr2_ps = (const float*)d_in[15];
    const float* b2_ps  = (const float*)d_in[16];

    const int NS = in_sizes[0] / HF;
    const int NP = in_sizes[1];
    const int E  = in_sizes[2];

    float *xplay, *p1, *s1, *invP, *invS;
    int *cntP, *cntS, *offP, *offS, *curP, *curS, *adjP, *adjS;
    __nv_bfloat16 *songHi,*songLo,*playHi,*playLo,*aggPHi,*aggPLo,*aggSHi,*aggSLo,*p1Hi,*p1Lo,*s1Hi,*s1Lo,*WHi,*WLo;
    cudaGetSymbolAddress((void**)&xplay, g_xplay);
    cudaGetSymbolAddress((void**)&p1,    g_p1);
    cudaGetSymbolAddress((void**)&s1,    g_s1);
    cudaGetSymbolAddress((void**)&invP,  g_invP);
    cudaGetSymbolAddress((void**)&invS,  g_invS);
    cudaGetSymbolAddress((void**)&cntP,  g_cntP);
    cudaGetSymbolAddress((void**)&cntS,  g_cntS);
    cudaGetSymbolAddress((void**)&offP,  g_offP);
    cudaGetSymbolAddress((void**)&offS,  g_offS);
    cudaGetSymbolAddress((void**)&curP,  g_curP);
    cudaGetSymbolAddress((void**)&curS,  g_curS);
    cudaGetSymbolAddress((void**)&adjP,  g_adjP);
    cudaGetSymbolAddress((void**)&adjS,  g_adjS);
    cudaGetSymbolAddress((void**)&songHi, g_songHi); cudaGetSymbolAddress((void**)&songLo, g_songLo);
    cudaGetSymbolAddress((void**)&playHi, g_playHi); cudaGetSymbolAddress((void**)&playLo, g_playLo);
    cudaGetSymbolAddress((void**)&aggPHi, g_aggPHi); cudaGetSymbolAddress((void**)&aggPLo, g_aggPLo);
    cudaGetSymbolAddress((void**)&aggSHi, g_aggSHi); cudaGetSymbolAddress((void**)&aggSLo, g_aggSLo);
    cudaGetSymbolAddress((void**)&p1Hi,   g_p1Hi);   cudaGetSymbolAddress((void**)&p1Lo,   g_p1Lo);
    cudaGetSymbolAddress((void**)&s1Hi,   g_s1Hi);   cudaGetSymbolAddress((void**)&s1Lo,   g_s1Lo);
    cudaGetSymbolAddress((void**)&WHi,    g_WHi);    cudaGetSymbolAddress((void**)&WLo,    g_WLo);

    float* out_s2 = (float*)d_out;
    float* out_p2 = (float*)d_out + (size_t)NS * HF;

    // one-time resources (no device memory involved)
    static cudaStream_t strA = 0, strB = 0;
    static cudaEvent_t evStart = 0, evFill = 0, evConv = 0, evS1 = 0, evP1 = 0, evA = 0, evB = 0;
    if (!strA) {
        cudaFuncSetAttribute(mma_dual_gemm, cudaFuncAttributeMaxDynamicSharedMemorySize, GEMM_SMEM);
        cudaStreamCreateWithFlags(&strA, cudaStreamNonBlocking);
        cudaStreamCreateWithFlags(&strB, cudaStreamNonBlocking);
        cudaEventCreateWithFlags(&evStart, cudaEventDisableTiming);
        cudaEventCreateWithFlags(&evFill,  cudaEventDisableTiming);
        cudaEventCreateWithFlags(&evConv,  cudaEventDisableTiming);
        cudaEventCreateWithFlags(&evS1,    cudaEventDisableTiming);
        cudaEventCreateWithFlags(&evP1,    cudaEventDisableTiming);
        cudaEventCreateWithFlags(&evA,     cudaEventDisableTiming);
        cudaEventCreateWithFlags(&evB,     cudaEventDisableTiming);
    }

    const int aggBlkP = (NP + 7) / 8;
    const int aggBlkS = (NS + 7) / 8;
    const int tileP = (NP + 127) / 128;
    const int tileS = (NS + 127) / 128;
    const size_t WSZ = (size_t)HF * 256;

    // ---- fork: conversions on strB, CSR build on stream 0 ----
    cudaEventRecord(evStart, 0);
    cudaStreamWaitEvent(strB, evStart, 0);
    cudaStreamWaitEvent(strA, evStart, 0);

    {   // strB: conversions (independent of CSR build)
        int Bg = (NP * 32 + 255) / 256;
        int Bc = (NS * HF / 4 + 255) / 256;
        convert_all<<<Bg + Bc + 512, 256, 0, strB>>>(pemb, pid, NP, xplay, playHi, playLo,
                                                     song_x, NS, songHi, songLo,
                                                     Wl1_sp, Wr1_sp, Wl1_ps, Wr1_ps,
                                                     Wl2_sp, Wr2_sp, Wl2_ps, Wr2_ps,
                                                     WHi, WLo, Bg, Bc);
        cudaEventRecord(evConv, strB);
    }

    // strA: CSR build chain
    zero_cnt<<<(NS + 255) / 256, 256, 0, strA>>>(cntP, NP, cntS, NS);
    count_kernel<<<(E + 255) / 256, 256, 0, strA>>>(es, ep, cntS, cntP, E);
    scan_inv_zero<<<2 + (NP + NS + 1023) / 1024, 1024, 0, strA>>>(cntP, offP, invP, NP,
                                                                  cntS, offS, invS, NS, curP, curS);
    fill_kernel<<<(E + 255) / 256, 256, 0, strA>>>(es, ep, offS, offP, curS, curP, adjS, adjP, E);
    cudaEventRecord(evFill, strA);

    // ---- layer 1: S-chain on strA, P-chain on strB ----
    // strA: aggS needs CSR (in-stream) + xplay (evConv); gemmS needs songHi/Lo (evConv)
    cudaStreamWaitEvent(strA, evConv, 0);
    csr_agg<<<aggBlkS, 256, 0, strA>>>(xplay, offS, adjS, invS, aggSHi, aggSLo, NS);
    mma_dual_gemm<<<tileS, 256, GEMM_SMEM, strA>>>(aggSHi, aggSLo, songHi, songLo,
                                                   WHi + 1 * WSZ, WLo + 1 * WSZ, b1_ps,
                                                   s1, s1Hi, s1Lo, NS, 1);
    cudaEventRecord(evS1, strA);

    // strB: aggP needs CSR (evFill) + song_x (input); gemmP needs playHi/Lo (in-stream)
    cudaStreamWaitEvent(strB, evFill, 0);
    csr_agg<<<aggBlkP, 256, 0, strB>>>(song_x, offP, adjP, invP, aggPHi, aggPLo, NP);
    mma_dual_gemm<<<tileP, 256, GEMM_SMEM, strB>>>(aggPHi, aggPLo, playHi, playLo,
                                                   WHi + 0 * WSZ, WLo + 0 * WSZ, b1_sp,
                                                   p1, p1Hi, p1Lo, NP, 1);
    cudaEventRecord(evP1, strB);

    // ---- layer 2: crossed dependencies ----
    // strA: S-side layer 2 needs p1 (strB) and s1Hi/Lo (in-stream)
    cudaStreamWaitEvent(strA, evP1, 0);
    csr_agg<<<aggBlkS, 256, 0, strA>>>(p1, offS, adjS, invS, aggSHi, aggSLo, NS);
    mma_dual_gemm<<<tileS, 256, GEMM_SMEM, strA>>>(aggSHi, aggSLo, s1Hi, s1Lo,
                                                   WHi + 3 * WSZ, WLo + 3 * WSZ, b2_ps,
                                                   out_s2, ((__nv_bfloat16*)0), ((__nv_bfloat16*)0), NS, 0);
    cudaEventRecord(evA, strA);

    // strB: P-side layer 2 needs s1 (strA) and p1Hi/Lo (in-stream)
    cudaStreamWaitEvent(strB, evS1, 0);
    csr_agg<<<aggBlkP, 256, 0, strB>>>(s1, offP, adjP, invP, aggPHi, aggPLo, NP);
    mma_dual_gemm<<<tileP, 256, GEMM_SMEM, strB>>>(aggPHi, aggPLo, p1Hi, p1Lo,
                                                   WHi + 2 * WSZ, WLo + 2 * WSZ, b2_sp,
                                                   out_p2, ((__nv_bfloat16*)0), ((__nv_bfloat16*)0), NP, 0);
    cudaEventRecord(evB, strB);

    // ---- join back to the capture origin stream ----
    cudaStreamWaitEvent(0, evA, 0);
    cudaStreamWaitEvent(0, evB, 0);
}

// round 11
// speedup vs baseline: 2.0357x; 1.1510x over previous
#include <cuda_runtime.h>
#include <cuda_bf16.h>
#include <cstdint>

#define NS_MAX 100000
#define NP_MAX 20000
#define E_MAX  500000
#define HF 128

// ======================= device scratch (no allocation allowed) ==============
__device__ float g_xplay[NP_MAX * HF];
__device__ float g_p1   [NP_MAX * HF];
__device__ float g_s1   [NS_MAX * HF];

__device__ __nv_bfloat16 g_songHi[NS_MAX * HF], g_songLo[NS_MAX * HF];
__device__ __nv_bfloat16 g_playHi[NP_MAX * HF], g_playLo[NP_MAX * HF];
__device__ __nv_bfloat16 g_aggPHi[NP_MAX * HF], g_aggPLo[NP_MAX * HF];
__device__ __nv_bfloat16 g_aggSHi[NS_MAX * HF], g_aggSLo[NS_MAX * HF];
__device__ __nv_bfloat16 g_p1Hi  [NP_MAX * HF], g_p1Lo  [NP_MAX * HF];
__device__ __nv_bfloat16 g_s1Hi  [NS_MAX * HF], g_s1Lo  [NS_MAX * HF];
__device__ __nv_bfloat16 g_WHi[4][HF * 256], g_WLo[4][HF * 256];  // B[n][k], k = concat(Wl,Wr)

__device__ int g_cntP[NP_MAX], g_cntS[NS_MAX];
__device__ int g_offP[NP_MAX], g_offS[NS_MAX];
__device__ int g_curP[NP_MAX], g_curS[NS_MAX];
__device__ int g_adjP[E_MAX], g_adjS[E_MAX];
__device__ int g_totP, g_totS;

// ======================= helpers =============================================
__device__ __forceinline__ uint32_t smem_u32(const void* p) {
    uint32_t a;
    asm("{ .reg .u64 t; cvta.to.shared.u64 t, %1; cvt.u32.u64 %0, t; }" : "=r"(a) : "l"(p));
    return a;
}
__device__ __forceinline__ uint32_t pack2bf(__nv_bfloat16 a, __nv_bfloat16 b) {
    return (uint32_t)__bfloat16_as_ushort(a) | ((uint32_t)__bfloat16_as_ushort(b) << 16);
}
__device__ __forceinline__ void split_f32(float x, __nv_bfloat16& h, __nv_bfloat16& l) {
    h = __float2bfloat16(x);
    l = __float2bfloat16(x - __bfloat162float(h));
}
__device__ __forceinline__ void ldsm_x4(uint32_t* r, uint32_t addr) {
    asm volatile("ldmatrix.sync.aligned.m8n8.x4.shared.b16 {%0,%1,%2,%3}, [%4];"
                 : "=r"(r[0]), "=r"(r[1]), "=r"(r[2]), "=r"(r[3]) : "r"(addr));
}
__device__ __forceinline__ void mma_bf16(float* d, const uint32_t* a, const uint32_t* b) {
    asm volatile("mma.sync.aligned.m16n8k16.row.col.f32.bf16.bf16.f32 "
                 "{%0,%1,%2,%3}, {%4,%5,%6,%7}, {%8,%9}, {%0,%1,%2,%3};"
                 : "+f"(d[0]), "+f"(d[1]), "+f"(d[2]), "+f"(d[3])
                 : "r"(a[0]), "r"(a[1]), "r"(a[2]), "r"(a[3]), "r"(b[0]), "r"(b[1]));
}

// ======================= graph-structure build ===============================
__global__ void zero_cnt(int* __restrict__ cntP, int nP, int* __restrict__ cntS, int nS,
                         int* __restrict__ totP, int* __restrict__ totS) {
    int i = blockIdx.x * blockDim.x + threadIdx.x;
    if (i < nP) cntP[i] = 0;
    if (i < nS) cntS[i] = 0;
    if (i == 0) { *totP = 0; *totS = 0; }
}

__global__ void count_kernel(const int* __restrict__ es, const int* __restrict__ ep,
                             int* __restrict__ cntS, int* __restrict__ cntP, int E) {
    int i = blockIdx.x * blockDim.x + threadIdx.x;
    if (i >= E) return;
    atomicAdd(&cntS[es[i]], 1);
    atomicAdd(&cntP[ep[i]], 1);
}

// parallel CSR allocation: block scan + one atomicAdd of block total.
// offsets land in arbitrary block order (fine: csr_agg uses off+cnt, not off[i+1]).
__device__ __forceinline__ void alloc_seg(const int* __restrict__ cnt, int* __restrict__ off,
                                          int* __restrict__ cur, int n, int* __restrict__ gTot,
                                          int blk) {
    __shared__ int wsum[8];
    __shared__ int blockBase;
    const int tid = threadIdx.x, lane = tid & 31, wid = tid >> 5;
    int i = blk * 256 + tid;
    int v = (i < n) ? cnt[i] : 0;
    int x = v;
    #pragma unroll
    for (int d = 1; d < 32; d <<= 1) { int y = __shfl_up_sync(~0u, x, d); if (lane >= d) x += y; }
    if (lane == 31) wsum[wid] = x;
    __syncthreads();
    if (wid == 0) {
        int ws = (lane < 8) ? wsum[lane] : 0;
        #pragma unroll
        for (int d = 1; d < 8; d <<= 1) { int y = __shfl_up_sync(~0u, ws, d); if (lane >= d) ws += y; }
        if (lane < 8) wsum[lane] = ws;
    }
    __syncthreads();
    int excl = (x - v) + (wid > 0 ? wsum[wid - 1] : 0);
    if (tid == 0) blockBase = atomicAdd(gTot, wsum[7]);
    __syncthreads();
    if (i < n) { int base = blockBase + excl; off[i] = base; cur[i] = base; }
}

__global__ void alloc_kernel(const int* cntP, int* offP, int* curP, int nP, int* totP,
                             const int* cntS, int* offS, int* curS, int nS, int* totS,
                             int BP) {
    if ((int)blockIdx.x < BP) alloc_seg(cntP, offP, curP, nP, totP, blockIdx.x);
    else                      alloc_seg(cntS, offS, curS, nS, totS, blockIdx.x - BP);
}

__global__ void fill_kernel(const int* __restrict__ es, const int* __restrict__ ep,
                            int* __restrict__ curS, int* __restrict__ curP,
                            int* __restrict__ adjS, int* __restrict__ adjP, int E) {
    int i = blockIdx.x * blockDim.x + threadIdx.x;
    if (i >= E) return;
    int s = es[i], p = ep[i];
    int ps = atomicAdd(&curS[s], 1); adjS[ps] = p;
    int pp = atomicAdd(&curP[p], 1); adjP[pp] = s;
}

// ======================= all conversions fused ===============================
__global__ void convert_all(const float* __restrict__ pe, const int* __restrict__ pid, int NP,
                            float* __restrict__ xplayF,
                            __nv_bfloat16* __restrict__ playHi, __nv_bfloat16* __restrict__ playLo,
                            const float* __restrict__ song, int NS,
                            __nv_bfloat16* __restrict__ songHi, __nv_bfloat16* __restrict__ songLo,
                            const float* Wl0, const float* Wr0, const float* Wl1, const float* Wr1,
                            const float* Wl2, const float* Wr2, const float* Wl3, const float* Wr3,
                            __nv_bfloat16* __restrict__ WHi, __nv_bfloat16* __restrict__ WLo,
                            int Bg, int Bc) {
    int b = blockIdx.x;
    if (b < Bg) {
        int t = b * blockDim.x + threadIdx.x;
        int row = t >> 5, lane = t & 31;
        if (row >= NP) return;
        float4 v = __ldg((const float4*)(pe + (size_t)pid[row] * HF) + lane);
        ((float4*)(xplayF + (size_t)row * HF))[lane] = v;
        __nv_bfloat16 h0,h1,h2,h3,l0,l1,l2,l3;
        split_f32(v.x,h0,l0); split_f32(v.y,h1,l1); split_f32(v.z,h2,l2); split_f32(v.w,h3,l3);
        ((uint2*)(playHi + (size_t)row * HF))[lane] = make_uint2(pack2bf(h0,h1), pack2bf(h2,h3));
        ((uint2*)(playLo + (size_t)row * HF))[lane] = make_uint2(pack2bf(l0,l1), pack2bf(l2,l3));
    } else if (b < Bg + Bc) {
        int i = (b - Bg) * blockDim.x + threadIdx.x;
        if (i >= NS * HF / 4) return;
        float4 v = __ldg((const float4*)song + i);
        __nv_bfloat16 h0,h1,h2,h3,l0,l1,l2,l3;
        split_f32(v.x,h0,l0); split_f32(v.y,h1,l1); split_f32(v.z,h2,l2); split_f32(v.w,h3,l3);
        ((uint2*)songHi)[i] = make_uint2(pack2bf(h0,h1), pack2bf(h2,h3));
        ((uint2*)songLo)[i] = make_uint2(pack2bf(l0,l1), pack2bf(l2,l3));
    } else {
        int lb = b - Bg - Bc;                    // 0..511
        int pair = lb >> 7;
        int idx = (lb & 127) * 256 + threadIdx.x;
        const float* Wl = pair == 0 ? Wl0 : pair == 1 ? Wl1 : pair == 2 ? Wl2 : Wl3;
        const float* Wr = pair == 0 ? Wr0 : pair == 1 ? Wr1 : pair == 2 ? Wr2 : Wr3;
        int k = idx & 255, n = idx >> 8;
        float w = (k < 128) ? Wl[(size_t)k * HF + n] : Wr[(size_t)(k - 128) * HF + n];
        __nv_bfloat16 h, l; split_f32(w, h, l);
        WHi[(size_t)pair * HF * 256 + (size_t)n * 256 + k] = h;
        WLo[(size_t)pair * HF * 256 + (size_t)n * 256 + k] = l;
    }
}

// ======================= CSR mean-aggregation (fp32 in, bf16 hi/lo out) ======
__global__ void csr_agg(const float* __restrict__ src,
                        const int* __restrict__ off, const int* __restrict__ cnt,
                        const int* __restrict__ adj,
                        __nv_bfloat16* __restrict__ outHi, __nv_bfloat16* __restrict__ outLo,
                        int Ndst) {
    int warp = (blockIdx.x * blockDim.x + threadIdx.x) >> 5;
    int lane = threadIdx.x & 31;
    if (warp >= Ndst) return;
    int s0 = off[warp];
    int c  = cnt[warp];
    int s1 = s0 + c;
    float4 acc = make_float4(0.f, 0.f, 0.f, 0.f);
    for (int e = s0; e < s1; e += 32) {
        int myE = e + lane;
        int myIdx = (myE < s1) ? __ldg(adj + myE) : 0;
        int n = min(32, s1 - e);
        for (int j = 0; j < n; j++) {
            int sidx = __shfl_sync(~0u, myIdx, j);
            float4 v = __ldg(((const float4*)src) + (size_t)sidx * 32 + lane);
            acc.x += v.x; acc.y += v.y; acc.z += v.z; acc.w += v.w;
        }
    }
    float w = 1.0f / (float)max(c, 1);
    acc.x *= w; acc.y *= w; acc.z *= w; acc.w *= w;
    __nv_bfloat16 h0,h1,h2,h3,l0,l1,l2,l3;
    split_f32(acc.x,h0,l0); split_f32(acc.y,h1,l1); split_f32(acc.z,h2,l2); split_f32(acc.w,h3,l3);
    ((uint2*)(outHi + (size_t)warp * HF))[lane] = make_uint2(pack2bf(h0,h1), pack2bf(h2,h3));
    ((uint2*)(outLo + (size_t)warp * HF))[lane] = make_uint2(pack2bf(l0,l1), pack2bf(l2,l3));
}

// ======================= mma.sync split-bf16 dual GEMM =======================
#define GEMM_SMEM 65536
#define OFF_AH 0
#define OFF_AL 16384
#define OFF_BH 32768
#define OFF_BL 49152

__device__ __forceinline__ int sw_off(int r, int q) {
    return r * 128 + ((q ^ (r & 7)) << 4);
}

__global__ __launch_bounds__(256, 2)
void mma_dual_gemm(const __nv_bfloat16* __restrict__ A1Hi, const __nv_bfloat16* __restrict__ A1Lo,
                   const __nv_bfloat16* __restrict__ A2Hi, const __nv_bfloat16* __restrict__ A2Lo,
                   const __nv_bfloat16* __restrict__ BHi,  const __nv_bfloat16* __restrict__ BLo,
                   const float* __restrict__ bias,
                   float* __restrict__ outF,
                   __nv_bfloat16* __restrict__ outHi, __nv_bfloat16* __restrict__ outLo,
                   int N, int doRelu) {
    extern __shared__ char smem[];
    const uint32_t sb = smem_u32(smem);
    const int tid = threadIdx.x, wid = tid >> 5, lane = tid & 31;
    const int rowBase = blockIdx.x * 128;

    const int mBase = (wid & 3) * 32;
    const int nBase = (wid >> 2) * 64;

    float acc[2][8][4];
    #pragma unroll
    for (int mt = 0; mt < 2; mt++)
        #pragma unroll
        for (int nt = 0; nt < 8; nt++)
            #pragma unroll
            for (int j = 0; j < 4; j++) acc[mt][nt][j] = 0.f;

    const int rowA  = mBase + (lane & 15);
    const int partA = lane >> 4;
    const int swA   = rowA & 7;
    const int rowB  = nBase + ((lane >> 4) << 3) + (lane & 7);
    const int partB = (lane >> 3) & 1;
    const int swB   = rowB & 7;

    #pragma unroll 1
    for (int c = 0; c < 4; c++) {
        const __nv_bfloat16* AH = (c < 2) ? A1Hi : A2Hi;
        const __nv_bfloat16* AL = (c < 2) ? A1Lo : A2Lo;
        const int kA = (c & 1) * 64;
        const int kB = c * 64;

        __syncthreads();
        #pragma unroll
        for (int u = 0; u < 4; u++) {
            int idx = tid + u * 256;
            int r = idx >> 3, q = idx & 7;
            int gr = rowBase + r;
            uint4 vah, val;
            if (gr < N) {
                vah = __ldg((const uint4*)(AH + (size_t)gr * HF + kA) + q);
                val = __ldg((const uint4*)(AL + (size_t)gr * HF + kA) + q);
            } else { vah = make_uint4(0,0,0,0); val = vah; }
            uint4 vbh = __ldg((const uint4*)(BHi + (size_t)r * 256 + kB) + q);
            uint4 vbl = __ldg((const uint4*)(BLo + (size_t)r * 256 + kB) + q);
            int so = sw_off(r, q);
            *(uint4*)(smem + OFF_AH + so) = vah;
            *(uint4*)(smem + OFF_AL + so) = val;
            *(uint4*)(smem + OFF_BH + so) = vbh;
            *(uint4*)(smem + OFF_BL + so) = vbl;
        }
        __syncthreads();

        #pragma unroll
        for (int ks = 0; ks < 4; ks++) {
            uint32_t ah[2][4], al[2][4], b[8][2];
            const int qa = ((ks * 2 + partA) ^ swA) << 4;
            const int qb = ((ks * 2 + partB) ^ swB) << 4;
            #pragma unroll
            for (int mt = 0; mt < 2; mt++) {
                ldsm_x4(ah[mt], sb + OFF_AH + (rowA + mt * 16) * 128 + qa);
                ldsm_x4(al[mt], sb + OFF_AL + (rowA + mt * 16) * 128 + qa);
            }
            #pragma unroll
            for (int p = 0; p < 4; p++)
                ldsm_x4(&b[p * 2][0], sb + OFF_BH + (rowB + p * 16) * 128 + qb);
            #pragma unroll
            for (int mt = 0; mt < 2; mt++)
                #pragma unroll
                for (int nt = 0; nt < 8; nt++)
                    mma_bf16(acc[mt][nt], ah[mt], b[nt]);
            #pragma unroll
            for (int mt = 0; mt < 2; mt++)
                #pragma unroll
                for (int nt = 0; nt < 8; nt++)
                    mma_bf16(acc[mt][nt], al[mt], b[nt]);
            #pragma unroll
            for (int p = 0; p < 4; p++)
                ldsm_x4(&b[p * 2][0], sb + OFF_BL + (rowB + p * 16) * 128 + qb);
            #pragma unroll
            for (int mt = 0; mt < 2; mt++)
                #pragma unroll
                for (int nt = 0; nt < 8; nt++)
                    mma_bf16(acc[mt][nt], ah[mt], b[nt]);
        }
    }

    const int erow = lane >> 2;
    const int ecol = (lane & 3) * 2;
    #pragma unroll
    for (int mt = 0; mt < 2; mt++) {
        #pragma unroll
        for (int nt = 0; nt < 8; nt++) {
            int col = nBase + nt * 8 + ecol;
            float2 bb = *(const float2*)(bias + col);
            #pragma unroll
            for (int h = 0; h < 2; h++) {
                int gr = rowBase + mBase + mt * 16 + erow + h * 8;
                if (gr < N) {
                    float x0 = acc[mt][nt][h * 2 + 0] + bb.x;
                    float x1 = acc[mt][nt][h * 2 + 1] + bb.y;
                    if (doRelu) { x0 = fmaxf(x0, 0.f); x1 = fmaxf(x1, 0.f); }
                    *(float2*)(outF + (size_t)gr * HF + col) = make_float2(x0, x1);
                    if (outHi) {
                        __nv_bfloat16 h0, h1, l0, l1;
                        split_f32(x0, h0, l0); split_f32(x1, h1, l1);
                        *(uint32_t*)(outHi + (size_t)gr * HF + col) = pack2bf(h0, h1);
                        *(uint32_t*)(outLo + (size_t)gr * HF + col) = pack2bf(l0, l1);
                    }
                }
            }
        }
    }
}

// ======================= launch (fork-join multi-stream graph) ===============
extern "C" void kernel_launch(void* const* d_in, const int* in_sizes, int n_in,
                              void* d_out, int out_size) {
    const float* song_x = (const float*)d_in[0];
    const int*   pid    = (const int*)  d_in[1];
    const int*   es     = (const int*)  d_in[2];
    const int*   ep     = (const int*)  d_in[3];
    const float* pemb   = (const float*)d_in[4];
    const float* Wl1_sp = (const float*)d_in[5];
    const float* Wr1_sp = (const float*)d_in[6];
    const float* b1_sp  = (const float*)d_in[7];
    const float* Wl1_ps = (const float*)d_in[8];
    const float* Wr1_ps = (const float*)d_in[9];
    const float* b1_ps  = (const float*)d_in[10];
    const float* Wl2_sp = (const float*)d_in[11];
    const float* Wr2_sp = (const float*)d_in[12];
    const float* b2_sp  = (const float*)d_in[13];
    const float* Wl2_ps = (const float*)d_in[14];
    const float* Wr2_ps = (const float*)d_in[15];
    const float* b2_ps  = (const float*)d_in[16];

    const int NS = in_sizes[0] / HF;
    const int NP = in_sizes[1];
    const int E  = in_sizes[2];

    float *xplay, *p1, *s1;
    int *cntP, *cntS, *offP, *offS, *curP, *curS, *adjP, *adjS, *totP, *totS;
    __nv_bfloat16 *songHi,*songLo,*playHi,*playLo,*aggPHi,*aggPLo,*aggSHi,*aggSLo,*p1Hi,*p1Lo,*s1Hi,*s1Lo,*WHi,*WLo;
    cudaGetSymbolAddress((void**)&xplay, g_xplay);
    cudaGetSymbolAddress((void**)&p1,    g_p1);
    cudaGetSymbolAddress((void**)&s1,    g_s1);
    cudaGetSymbolAddress((void**)&cntP,  g_cntP);
    cudaGetSymbolAddress((void**)&cntS,  g_cntS);
    cudaGetSymbolAddress((void**)&offP,  g_offP);
    cudaGetSymbolAddress((void**)&offS,  g_offS);
    cudaGetSymbolAddress((void**)&curP,  g_curP);
    cudaGetSymbolAddress((void**)&curS,  g_curS);
    cudaGetSymbolAddress((void**)&adjP,  g_adjP);
    cudaGetSymbolAddress((void**)&adjS,  g_adjS);
    cudaGetSymbolAddress((void**)&totP,  g_totP);
    cudaGetSymbolAddress((void**)&totS,  g_totS);
    cudaGetSymbolAddress((void**)&songHi, g_songHi); cudaGetSymbolAddress((void**)&songLo, g_songLo);
    cudaGetSymbolAddress((void**)&playHi, g_playHi); cudaGetSymbolAddress((void**)&playLo, g_playLo);
    cudaGetSymbolAddress((void**)&aggPHi, g_aggPHi); cudaGetSymbolAddress((void**)&aggPLo, g_aggPLo);
    cudaGetSymbolAddress((void**)&aggSHi, g_aggSHi); cudaGetSymbolAddress((void**)&aggSLo, g_aggSLo);
    cudaGetSymbolAddress((void**)&p1Hi,   g_p1Hi);   cudaGetSymbolAddress((void**)&p1Lo,   g_p1Lo);
    cudaGetSymbolAddress((void**)&s1Hi,   g_s1Hi);   cudaGetSymbolAddress((void**)&s1Lo,   g_s1Lo);
    cudaGetSymbolAddress((void**)&WHi,    g_WHi);    cudaGetSymbolAddress((void**)&WLo,    g_WLo);

    float* out_s2 = (float*)d_out;
    float* out_p2 = (float*)d_out + (size_t)NS * HF;

    // one-time resources (no device memory involved)
    static cudaStream_t strA = 0, strB = 0;
    static cudaEvent_t evStart = 0, evFill = 0, evConv = 0, evS1 = 0, evP1 = 0, evA = 0, evB = 0;
    if (!strA) {
        cudaFuncSetAttribute(mma_dual_gemm, cudaFuncAttributeMaxDynamicSharedMemorySize, GEMM_SMEM);
        cudaStreamCreateWithFlags(&strA, cudaStreamNonBlocking);
        cudaStreamCreateWithFlags(&strB, cudaStreamNonBlocking);
        cudaEventCreateWithFlags(&evStart, cudaEventDisableTiming);
        cudaEventCreateWithFlags(&evFill,  cudaEventDisableTiming);
        cudaEventCreateWithFlags(&evConv,  cudaEventDisableTiming);
        cudaEventCreateWithFlags(&evS1,    cudaEventDisableTiming);
        cudaEventCreateWithFlags(&evP1,    cudaEventDisableTiming);
        cudaEventCreateWithFlags(&evA,     cudaEventDisableTiming);
        cudaEventCreateWithFlags(&evB,     cudaEventDisableTiming);
    }

    const int aggBlkP = (NP + 7) / 8;
    const int aggBlkS = (NS + 7) / 8;
    const int tileP = (NP + 127) / 128;
    const int tileS = (NS + 127) / 128;
    const size_t WSZ = (size_t)HF * 256;

    // ---- fork: conversions on strB, CSR build on strA ----
    cudaEventRecord(evStart, 0);
    cudaStreamWaitEvent(strB, evStart, 0);
    cudaStreamWaitEvent(strA, evStart, 0);

    {   // strB: conversions (independent of CSR build)
        int Bg = (NP * 32 + 255) / 256;
        int Bc = (NS * HF / 4 + 255) / 256;
        convert_all<<<Bg + Bc + 512, 256, 0, strB>>>(pemb, pid, NP, xplay, playHi, playLo,
                                                     song_x, NS, songHi, songLo,
                                                     Wl1_sp, Wr1_sp, Wl1_ps, Wr1_ps,
                                                     Wl2_sp, Wr2_sp, Wl2_ps, Wr2_ps,
                                                     WHi, WLo, Bg, Bc);
        cudaEventRecord(evConv, strB);
    }

    // strA: CSR build chain (scan replaced by parallel block-aggregated alloc)
    zero_cnt<<<(NS + 255) / 256, 256, 0, strA>>>(cntP, NP, cntS, NS, totP, totS);
    count_kernel<<<(E + 255) / 256, 256, 0, strA>>>(es, ep, cntS, cntP, E);
    {
        int BP = (NP + 255) / 256, BS = (NS + 255) / 256;
        alloc_kernel<<<BP + BS, 256, 0, strA>>>(cntP, offP, curP, NP, totP,
                                                cntS, offS, curS, NS, totS, BP);
    }
    fill_kernel<<<(E + 255) / 256, 256, 0, strA>>>(es, ep, curS, curP, adjS, adjP, E);
    cudaEventRecord(evFill, strA);

    // ---- layer 1: S-chain on strA, P-chain on strB ----
    cudaStreamWaitEvent(strA, evConv, 0);
    csr_agg<<<aggBlkS, 256, 0, strA>>>(xplay, offS, cntS, adjS, aggSHi, aggSLo, NS);
    mma_dual_gemm<<<tileS, 256, GEMM_SMEM, strA>>>(aggSHi, aggSLo, songHi, songLo,
                                                   WHi + 1 * WSZ, WLo + 1 * WSZ, b1_ps,
                                                   s1, s1Hi, s1Lo, NS, 1);
    cudaEventRecord(evS1, strA);

    cudaStreamWaitEvent(strB, evFill, 0);
    csr_agg<<<aggBlkP, 256, 0, strB>>>(song_x, offP, cntP, adjP, aggPHi, aggPLo, NP);
    mma_dual_gemm<<<tileP, 256, GEMM_SMEM, strB>>>(aggPHi, aggPLo, playHi, playLo,
                                                   WHi + 0 * WSZ, WLo + 0 * WSZ, b1_sp,
                                                   p1, p1Hi, p1Lo, NP, 1);
    cudaEventRecord(evP1, strB);

    // ---- layer 2: crossed dependencies ----
    cudaStreamWaitEvent(strA, evP1, 0);
    csr_agg<<<aggBlkS, 256, 0, strA>>>(p1, offS, cntS, adjS, aggSHi, aggSLo, NS);
    mma_dual_gemm<<<tileS, 256, GEMM_SMEM, strA>>>(aggSHi, aggSLo, s1Hi, s1Lo,
                                                   WHi + 3 * WSZ, WLo + 3 * WSZ, b2_ps,
                                                   out_s2, ((__nv_bfloat16*)0), ((__nv_bfloat16*)0), NS, 0);
    cudaEventRecord(evA, strA);

    cudaStreamWaitEvent(strB, evS1, 0);
    csr_agg<<<aggBlkP, 256, 0, strB>>>(s1, offP, cntP, adjP, aggPHi, aggPLo, NP);
    mma_dual_gemm<<<tileP, 256, GEMM_SMEM, strB>>>(aggPHi, aggPLo, p1Hi, p1Lo,
                                                   WHi + 2 * WSZ, WLo + 2 * WSZ, b2_sp,
                                                   out_p2, ((__nv_bfloat16*)0), ((__nv_bfloat16*)0), NP, 0);
    cudaEventRecord(evB, strB);

    // ---- join back to the capture origin stream ----
    cudaStreamWaitEvent(0, evA, 0);
    cudaStreamWaitEvent(0, evB, 0);
}

// round 13
// speedup vs baseline: 2.8540x; 1.4020x over previous
#include <cuda_runtime.h>
#include <cuda_fp16.h>
#include <cstdint>

#define NS_MAX 100000
#define NP_MAX 20000
#define E_MAX  500000
#define HF 128

// ======================= device scratch (no allocation allowed) ==============
__device__ float g_xplay[NP_MAX * HF];
__device__ float g_p1   [NP_MAX * HF];
__device__ float g_s1   [NS_MAX * HF];

__device__ __half g_song16[NS_MAX * HF];
__device__ __half g_play16[NP_MAX * HF];
__device__ __half g_aggP16[NP_MAX * HF];
__device__ __half g_aggS16[NS_MAX * HF];
__device__ __half g_p116  [NP_MAX * HF];
__device__ __half g_s116  [NS_MAX * HF];
__device__ __half g_W16[4][HF * 256];   // B[n][k], k = concat(Wl,Wr), fp16

__device__ int g_cntP[NP_MAX], g_cntS[NS_MAX];
__device__ int g_offP[NP_MAX], g_offS[NS_MAX];
__device__ int g_curP[NP_MAX], g_curS[NS_MAX];
__device__ int g_adjP[E_MAX], g_adjS[E_MAX];
__device__ int g_totP, g_totS;

// ======================= helpers =============================================
__device__ __forceinline__ uint32_t smem_u32(const void* p) {
    uint32_t a;
    asm("{ .reg .u64 t; cvta.to.shared.u64 t, %1; cvt.u32.u64 %0, t; }" : "=r"(a) : "l"(p));
    return a;
}
__device__ __forceinline__ uint32_t pack2h(float a, float b) {
    __half2 h = __floats2half2_rn(a, b);
    return *(uint32_t*)&h;
}
__device__ __forceinline__ void ldsm_x4(uint32_t* r, uint32_t addr) {
    asm volatile("ldmatrix.sync.aligned.m8n8.x4.shared.b16 {%0,%1,%2,%3}, [%4];"
                 : "=r"(r[0]), "=r"(r[1]), "=r"(r[2]), "=r"(r[3]) : "r"(addr));
}
__device__ __forceinline__ void mma_f16(float* d, const uint32_t* a, const uint32_t* b) {
    asm volatile("mma.sync.aligned.m16n8k16.row.col.f32.f16.f16.f32 "
                 "{%0,%1,%2,%3}, {%4,%5,%6,%7}, {%8,%9}, {%0,%1,%2,%3};"
                 : "+f"(d[0]), "+f"(d[1]), "+f"(d[2]), "+f"(d[3])
                 : "r"(a[0]), "r"(a[1]), "r"(a[2]), "r"(a[3]), "r"(b[0]), "r"(b[1]));
}

// ======================= graph-structure build ===============================
__global__ void zero_cnt(int* __restrict__ cntP, int nP, int* __restrict__ cntS, int nS,
                         int* __restrict__ totP, int* __restrict__ totS) {
    int i = blockIdx.x * blockDim.x + threadIdx.x;
    if (i < nP) cntP[i] = 0;
    if (i < nS) cntS[i] = 0;
    if (i == 0) { *totP = 0; *totS = 0; }
}

__global__ void count_kernel(const int* __restrict__ es, const int* __restrict__ ep,
                             int* __restrict__ cntS, int* __restrict__ cntP, int E) {
    int i = blockIdx.x * blockDim.x + threadIdx.x;
    if (i >= E) return;
    atomicAdd(&cntS[es[i]], 1);
    atomicAdd(&cntP[ep[i]], 1);
}

// parallel CSR allocation: block scan + one atomicAdd of block total.
// offsets land in arbitrary block order (fine: csr_agg uses off+cnt, not off[i+1]).
__device__ __forceinline__ void alloc_seg(const int* __restrict__ cnt, int* __restrict__ off,
                                          int* __restrict__ cur, int n, int* __restrict__ gTot,
                                          int blk) {
    __shared__ int wsum[8];
    __shared__ int blockBase;
    const int tid = threadIdx.x, lane = tid & 31, wid = tid >> 5;
    int i = blk * 256 + tid;
    int v = (i < n) ? cnt[i] : 0;
    int x = v;
    #pragma unroll
    for (int d = 1; d < 32; d <<= 1) { int y = __shfl_up_sync(~0u, x, d); if (lane >= d) x += y; }
    if (lane == 31) wsum[wid] = x;
    __syncthreads();
    if (wid == 0) {
        int ws = (lane < 8) ? wsum[lane] : 0;
        #pragma unroll
        for (int d = 1; d < 8; d <<= 1) { int y = __shfl_up_sync(~0u, ws, d); if (lane >= d) ws += y; }
        if (lane < 8) wsum[lane] = ws;
    }
    __syncthreads();
    int excl = (x - v) + (wid > 0 ? wsum[wid - 1] : 0);
    if (tid == 0) blockBase = atomicAdd(gTot, wsum[7]);
    __syncthreads();
    if (i < n) { int base = blockBase + excl; off[i] = base; cur[i] = base; }
}

__global__ void alloc_kernel(const int* cntP, int* offP, int* curP, int nP, int* totP,
                             const int* cntS, int* offS, int* curS, int nS, int* totS,
                             int BP) {
    if ((int)blockIdx.x < BP) alloc_seg(cntP, offP, curP, nP, totP, blockIdx.x);
    else                      alloc_seg(cntS, offS, curS, nS, totS, blockIdx.x - BP);
}

__global__ void fill_kernel(const int* __restrict__ es, const int* __restrict__ ep,
                            int* __restrict__ curS, int* __restrict__ curP,
                            int* __restrict__ adjS, int* __restrict__ adjP, int E) {
    int i = blockIdx.x * blockDim.x + threadIdx.x;
    if (i >= E) return;
    int s = es[i], p = ep[i];
    int ps = atomicAdd(&curS[s], 1); adjS[ps] = p;
    int pp = atomicAdd(&curP[p], 1); adjP[pp] = s;
}

// ======================= all conversions fused (fp32 -> fp16) ================
__global__ void convert_all(const float* __restrict__ pe, const int* __restrict__ pid, int NP,
                            float* __restrict__ xplayF, __half* __restrict__ play16,
                            const float* __restrict__ song, int NS, __half* __restrict__ song16,
                            const float* Wl0, const float* Wr0, const float* Wl1, const float* Wr1,
                            const float* Wl2, const float* Wr2, const float* Wl3, const float* Wr3,
                            __half* __restrict__ W16, int Bg, int Bc) {
    int b = blockIdx.x;
    if (b < Bg) {
        int t = b * blockDim.x + threadIdx.x;
        int row = t >> 5, lane = t & 31;
        if (row >= NP) return;
        float4 v = __ldg((const float4*)(pe + (size_t)pid[row] * HF) + lane);
        ((float4*)(xplayF + (size_t)row * HF))[lane] = v;
        ((uint2*)(play16 + (size_t)row * HF))[lane] = make_uint2(pack2h(v.x, v.y), pack2h(v.z, v.w));
    } else if (b < Bg + Bc) {
        int i = (b - Bg) * blockDim.x + threadIdx.x;
        if (i >= NS * HF / 4) return;
        float4 v = __ldg((const float4*)song + i);
        ((uint2*)song16)[i] = make_uint2(pack2h(v.x, v.y), pack2h(v.z, v.w));
    } else {
        int lb = b - Bg - Bc;                    // 0..511
        int pair = lb >> 7;
        int idx = (lb & 127) * 256 + threadIdx.x;
        const float* Wl = pair == 0 ? Wl0 : pair == 1 ? Wl1 : pair == 2 ? Wl2 : Wl3;
        const float* Wr = pair == 0 ? Wr0 : pair == 1 ? Wr1 : pair == 2 ? Wr2 : Wr3;
        int k = idx & 255, n = idx >> 8;
        float w = (k < 128) ? Wl[(size_t)k * HF + n] : Wr[(size_t)(k - 128) * HF + n];
        W16[(size_t)pair * HF * 256 + (size_t)n * 256 + k] = __float2half_rn(w);
    }
}

// ======================= CSR mean-aggregation (fp32 acc, fp16 out) ===========
__global__ void csr_agg(const float* __restrict__ src,
                        const int* __restrict__ off, const int* __restrict__ cnt,
                        const int* __restrict__ adj,
                        __half* __restrict__ out16, int Ndst) {
    int warp = (blockIdx.x * blockDim.x + threadIdx.x) >> 5;
    int lane = threadIdx.x & 31;
    if (warp >= Ndst) return;
    int s0 = off[warp];
    int c  = cnt[warp];
    int s1 = s0 + c;
    float4 acc = make_float4(0.f, 0.f, 0.f, 0.f);
    for (int e = s0; e < s1; e += 32) {
        int myE = e + lane;
        int myIdx = (myE < s1) ? __ldg(adj + myE) : 0;
        int n = min(32, s1 - e);
        for (int j = 0; j < n; j++) {
            int sidx = __shfl_sync(~0u, myIdx, j);
            float4 v = __ldg(((const float4*)src) + (size_t)sidx * 32 + lane);
            acc.x += v.x; acc.y += v.y; acc.z += v.z; acc.w += v.w;
        }
    }
    float w = 1.0f / (float)max(c, 1);
    acc.x *= w; acc.y *= w; acc.z *= w; acc.w *= w;
    ((uint2*)(out16 + (size_t)warp * HF))[lane] = make_uint2(pack2h(acc.x, acc.y), pack2h(acc.z, acc.w));
}

// ======================= mma.sync fp16 single-pass dual GEMM =================
// out = act(A1 @ Wl + b + A2 @ Wr).  Block tile 128x128, K-concat 256 in 4
// chunks of 64 (chunks 0-1: A1, 2-3: A2).  Single fp16 pass, fp32 accumulate.
// Per ks: 6 LDSM + 16 MMA.  SMEM: A 16KB + B 16KB.
#define GEMM_SMEM 32768
#define OFF_A 0
#define OFF_B 16384

__device__ __forceinline__ int sw_off(int r, int q) {
    return r * 128 + ((q ^ (r & 7)) << 4);
}

__global__ __launch_bounds__(256, 2)
void mma_dual_gemm(const __half* __restrict__ A1, const __half* __restrict__ A2,
                   const __half* __restrict__ B16,
                   const float* __restrict__ bias,
                   float* __restrict__ outF, __half* __restrict__ out16,
                   int N, int doRelu) {
    extern __shared__ char smem[];
    const uint32_t sb = smem_u32(smem);
    const int tid = threadIdx.x, wid = tid >> 5, lane = tid & 31;
    const int rowBase = blockIdx.x * 128;

    const int mBase = (wid & 3) * 32;
    const int nBase = (wid >> 2) * 64;

    float acc[2][8][4];
    #pragma unroll
    for (int mt = 0; mt < 2; mt++)
        #pragma unroll
        for (int nt = 0; nt < 8; nt++)
            #pragma unroll
            for (int j = 0; j < 4; j++) acc[mt][nt][j] = 0.f;

    const int rowA  = mBase + (lane & 15);
    const int partA = lane >> 4;
    const int swA   = rowA & 7;
    const int rowB  = nBase + ((lane >> 4) << 3) + (lane & 7);
    const int partB = (lane >> 3) & 1;
    const int swB   = rowB & 7;

    #pragma unroll 1
    for (int c = 0; c < 4; c++) {
        const __half* A = (c < 2) ? A1 : A2;
        const int kA = (c & 1) * 64;
        const int kB = c * 64;

        __syncthreads();   // previous chunk's compute done -> smem reusable
        #pragma unroll
        for (int u = 0; u < 4; u++) {
            int idx = tid + u * 256;          // 0..1023
            int r = idx >> 3, q = idx & 7;    // r: row 0..127, q: 16B quad 0..7
            int gr = rowBase + r;
            uint4 va = make_uint4(0, 0, 0, 0);
            if (gr < N) va = __ldg((const uint4*)(A + (size_t)gr * HF + kA) + q);
            uint4 vb = __ldg((const uint4*)(B16 + (size_t)r * 256 + kB) + q);
            int so = sw_off(r, q);
            *(uint4*)(smem + OFF_A + so) = va;
            *(uint4*)(smem + OFF_B + so) = vb;
        }
        __syncthreads();

        #pragma unroll
        for (int ks = 0; ks < 4; ks++) {
            uint32_t a[2][4], b[8][2];
            const int qa = ((ks * 2 + partA) ^ swA) << 4;
            const int qb = ((ks * 2 + partB) ^ swB) << 4;
            #pragma unroll
            for (int mt = 0; mt < 2; mt++)
                ldsm_x4(a[mt], sb + OFF_A + (rowA + mt * 16) * 128 + qa);
            #pragma unroll
            for (int p = 0; p < 4; p++)
                ldsm_x4(&b[p * 2][0], sb + OFF_B + (rowB + p * 16) * 128 + qb);
            #pragma unroll
            for (int mt = 0; mt < 2; mt++)
                #pragma unroll
                for (int nt = 0; nt < 8; nt++)
                    mma_f16(acc[mt][nt], a[mt], b[nt]);
        }
    }

    // ---- epilogue: bias (+relu), fp32 store, optional fp16 store ------------
    const int erow = lane >> 2;
    const int ecol = (lane & 3) * 2;
    #pragma unroll
    for (int mt = 0; mt < 2; mt++) {
        #pragma unroll
        for (int nt = 0; nt < 8; nt++) {
            int col = nBase + nt * 8 + ecol;
            float2 bb = *(const float2*)(bias + col);
            #pragma unroll
            for (int h = 0; h < 2; h++) {
                int gr = rowBase + mBase + mt * 16 + erow + h * 8;
                if (gr < N) {
                    float x0 = acc[mt][nt][h * 2 + 0] + bb.x;
                    float x1 = acc[mt][nt][h * 2 + 1] + bb.y;
                    if (doRelu) { x0 = fmaxf(x0, 0.f); x1 = fmaxf(x1, 0.f); }
                    *(float2*)(outF + (size_t)gr * HF + col) = make_float2(x0, x1);
                    if (out16)
                        *(uint32_t*)(out16 + (size_t)gr * HF + col) = pack2h(x0, x1);
                }
            }
        }
    }
}

// ======================= launch (fork-join multi-stream graph) ===============
extern "C" void kernel_launch(void* const* d_in, const int* in_sizes, int n_in,
                              void* d_out, int out_size) {
    const float* song_x = (const float*)d_in[0];
    const int*   pid    = (const int*)  d_in[1];
    const int*   es     = (const int*)  d_in[2];
    const int*   ep     = (const int*)  d_in[3];
    const float* pemb   = (const float*)d_in[4];
    const float* Wl1_sp = (const float*)d_in[5];
    const float* Wr1_sp = (const float*)d_in[6];
    const float* b1_sp  = (const float*)d_in[7];
    const float* Wl1_ps = (const float*)d_in[8];
    const float* Wr1_ps = (const float*)d_in[9];
    const float* b1_ps  = (const float*)d_in[10];
    const float* Wl2_sp = (const float*)d_in[11];
    const float* Wr2_sp = (const float*)d_in[12];
    const float* b2_sp  = (const float*)d_in[13];
    const float* Wl2_ps = (const float*)d_in[14];
    const float* Wr2_ps = (const float*)d_in[15];
    const float* b2_ps  = (const float*)d_in[16];

    const int NS = in_sizes[0] / HF;
    const int NP = in_sizes[1];
    const int E  = in_sizes[2];

    float *xplay, *p1, *s1;
    int *cntP, *cntS, *offP, *offS, *curP, *curS, *adjP, *adjS, *totP, *totS;
    __half *song16, *play16, *aggP16, *aggS16, *p116, *s116, *W16;
    cudaGetSymbolAddress((void**)&xplay, g_xplay);
    cudaGetSymbolAddress((void**)&p1,    g_p1);
    cudaGetSymbolAddress((void**)&s1,    g_s1);
    cudaGetSymbolAddress((void**)&cntP,  g_cntP);
    cudaGetSymbolAddress((void**)&cntS,  g_cntS);
    cudaGetSymbolAddress((void**)&offP,  g_offP);
    cudaGetSymbolAddress((void**)&offS,  g_offS);
    cudaGetSymbolAddress((void**)&curP,  g_curP);
    cudaGetSymbolAddress((void**)&curS,  g_curS);
    cudaGetSymbolAddress((void**)&adjP,  g_adjP);
    cudaGetSymbolAddress((void**)&adjS,  g_adjS);
    cudaGetSymbolAddress((void**)&totP,  g_totP);
    cudaGetSymbolAddress((void**)&totS,  g_totS);
    cudaGetSymbolAddress((void**)&song16, g_song16);
    cudaGetSymbolAddress((void**)&play16, g_play16);
    cudaGetSymbolAddress((void**)&aggP16, g_aggP16);
    cudaGetSymbolAddress((void**)&aggS16, g_aggS16);
    cudaGetSymbolAddress((void**)&p116,   g_p116);
    cudaGetSymbolAddress((void**)&s116,   g_s116);
    cudaGetSymbolAddress((void**)&W16,    g_W16);

    float* out_s2 = (float*)d_out;
    float* out_p2 = (float*)d_out + (size_t)NS * HF;

    // one-time resources (no device memory involved)
    static cudaStream_t strA = 0, strB = 0;
    static cudaEvent_t evStart = 0, evFill = 0, evConv = 0, evS1 = 0, evP1 = 0, evA = 0, evB = 0;
    if (!strA) {
        cudaFuncSetAttribute(mma_dual_gemm, cudaFuncAttributeMaxDynamicSharedMemorySize, GEMM_SMEM);
        cudaStreamCreateWithFlags(&strA, cudaStreamNonBlocking);
        cudaStreamCreateWithFlags(&strB, cudaStreamNonBlocking);
        cudaEventCreateWithFlags(&evStart, cudaEventDisableTiming);
        cudaEventCreateWithFlags(&evFill,  cudaEventDisableTiming);
        cudaEventCreateWithFlags(&evConv,  cudaEventDisableTiming);
        cudaEventCreateWithFlags(&evS1,    cudaEventDisableTiming);
        cudaEventCreateWithFlags(&evP1,    cudaEventDisableTiming);
        cudaEventCreateWithFlags(&evA,     cudaEventDisableTiming);
        cudaEventCreateWithFlags(&evB,     cudaEventDisableTiming);
    }

    const int aggBlkP = (NP + 7) / 8;
    const int aggBlkS = (NS + 7) / 8;
    const int tileP = (NP + 127) / 128;
    const int tileS = (NS + 127) / 128;
    const size_t WSZ = (size_t)HF * 256;

    // ---- fork: conversions on strB, CSR build on strA ----
    cudaEventRecord(evStart, 0);
    cudaStreamWaitEvent(strB, evStart, 0);
    cudaStreamWaitEvent(strA, evStart, 0);

    {   // strB: conversions (independent of CSR build)
        int Bg = (NP * 32 + 255) / 256;
        int Bc = (NS * HF / 4 + 255) / 256;
        convert_all<<<Bg + Bc + 512, 256, 0, strB>>>(pemb, pid, NP, xplay, play16,
                                                     song_x, NS, song16,
                                                     Wl1_sp, Wr1_sp, Wl1_ps, Wr1_ps,
                                                     Wl2_sp, Wr2_sp, Wl2_ps, Wr2_ps,
                                                     W16, Bg, Bc);
        cudaEventRecord(evConv, strB);
    }

    // strA: CSR build chain
    zero_cnt<<<(NS + 255) / 256, 256, 0, strA>>>(cntP, NP, cntS, NS, totP, totS);
    count_kernel<<<(E + 255) / 256, 256, 0, strA>>>(es, ep, cntS, cntP, E);
    {
        int BP = (NP + 255) / 256, BS = (NS + 255) / 256;
        alloc_kernel<<<BP + BS, 256, 0, strA>>>(cntP, offP, curP, NP, totP,
                                                cntS, offS, curS, NS, totS, BP);
    }
    fill_kernel<<<(E + 255) / 256, 256, 0, strA>>>(es, ep, curS, curP, adjS, adjP, E);
    cudaEventRecord(evFill, strA);

    // ---- layer 1: S-chain on strA, P-chain on strB ----
    cudaStreamWaitEvent(strA, evConv, 0);
    csr_agg<<<aggBlkS, 256, 0, strA>>>(xplay, offS, cntS, adjS, aggS16, NS);
    mma_dual_gemm<<<tileS, 256, GEMM_SMEM, strA>>>(aggS16, song16, W16 + 1 * WSZ, b1_ps,
                                                   s1, s116, NS, 1);
    cudaEventRecord(evS1, strA);

    cudaStreamWaitEvent(strB, evFill, 0);
    csr_agg<<<aggBlkP, 256, 0, strB>>>(song_x, offP, cntP, adjP, aggP16, NP);
    mma_dual_gemm<<<tileP, 256, GEMM_SMEM, strB>>>(aggP16, play16, W16 + 0 * WSZ, b1_sp,
                                                   p1, p116, NP, 1);
    cudaEventRecord(evP1, strB);

    // ---- layer 2: crossed dependencies ----
    cudaStreamWaitEvent(strA, evP1, 0);
    csr_agg<<<aggBlkS, 256, 0, strA>>>(p1, offS, cntS, adjS, aggS16, NS);
    mma_dual_gemm<<<tileS, 256, GEMM_SMEM, strA>>>(aggS16, s116, W16 + 3 * WSZ, b2_ps,
                                                   out_s2, ((__half*)0), NS, 0);
    cudaEventRecord(evA, strA);

    cudaStreamWaitEvent(strB, evS1, 0);
    csr_agg<<<aggBlkP, 256, 0, strB>>>(s1, offP, cntP, adjP, aggP16, NP);
    mma_dual_gemm<<<tileP, 256, GEMM_SMEM, strB>>>(aggP16, p116, W16 + 2 * WSZ, b2_sp,
                                                   out_p2, ((__half*)0), NP, 0);
    cudaEventRecord(evB, strB);

    // ---- join back to the capture origin stream ----
    cudaStreamWaitEvent(0, evA, 0);
    cudaStreamWaitEvent(0, evB, 0);
}

// round 14
// speedup vs baseline: 3.3555x; 1.1757x over previous
#include <cuda_runtime.h>
#include <cuda_fp16.h>
#include <cstdint>

#define NS_MAX 100000
#define NP_MAX 20000
#define E_MAX  500000
#define HF 128

// ======================= device scratch (no allocation allowed) ==============
__device__ __half g_song16[NS_MAX * HF];
__device__ __half g_play16[NP_MAX * HF];
__device__ __half g_aggP16[NP_MAX * HF];
__device__ __half g_aggS16[NS_MAX * HF];
__device__ __half g_p116  [NP_MAX * HF];
__device__ __half g_s116  [NS_MAX * HF];
__device__ __half g_W16[4][HF * 256];   // B[n][k], k = concat(Wl,Wr), fp16

__device__ int g_cntP[NP_MAX], g_cntS[NS_MAX];
__device__ int g_offP[NP_MAX], g_offS[NS_MAX];
__device__ int g_curP[NP_MAX], g_curS[NS_MAX];
__device__ int g_adjP[E_MAX], g_adjS[E_MAX];
__device__ int g_totP, g_totS;

// ======================= helpers =============================================
__device__ __forceinline__ uint32_t smem_u32(const void* p) {
    uint32_t a;
    asm("{ .reg .u64 t; cvta.to.shared.u64 t, %1; cvt.u32.u64 %0, t; }" : "=r"(a) : "l"(p));
    return a;
}
__device__ __forceinline__ uint32_t pack2h(float a, float b) {
    __half2 h = __floats2half2_rn(a, b);
    return *(uint32_t*)&h;
}
__device__ __forceinline__ void ldsm_x4(uint32_t* r, uint32_t addr) {
    asm volatile("ldmatrix.sync.aligned.m8n8.x4.shared.b16 {%0,%1,%2,%3}, [%4];"
                 : "=r"(r[0]), "=r"(r[1]), "=r"(r[2]), "=r"(r[3]) : "r"(addr));
}
__device__ __forceinline__ void mma_f16(float* d, const uint32_t* a, const uint32_t* b) {
    asm volatile("mma.sync.aligned.m16n8k16.row.col.f32.f16.f16.f32 "
                 "{%0,%1,%2,%3}, {%4,%5,%6,%7}, {%8,%9}, {%0,%1,%2,%3};"
                 : "+f"(d[0]), "+f"(d[1]), "+f"(d[2]), "+f"(d[3])
                 : "r"(a[0]), "r"(a[1]), "r"(a[2]), "r"(a[3]), "r"(b[0]), "r"(b[1]));
}

// ======================= graph-structure build ===============================
__global__ void zero_cnt(int* __restrict__ cntP, int nP, int* __restrict__ cntS, int nS,
                         int* __restrict__ totP, int* __restrict__ totS) {
    int i = blockIdx.x * blockDim.x + threadIdx.x;
    if (i < nP) cntP[i] = 0;
    if (i < nS) cntS[i] = 0;
    if (i == 0) { *totP = 0; *totS = 0; }
}

__global__ void count_kernel(const int* __restrict__ es, const int* __restrict__ ep,
                             int* __restrict__ cntS, int* __restrict__ cntP, int E) {
    int i = blockIdx.x * blockDim.x + threadIdx.x;
    if (i >= E) return;
    atomicAdd(&cntS[es[i]], 1);
    atomicAdd(&cntP[ep[i]], 1);
}

// parallel CSR allocation: block scan + one atomicAdd of block total.
__device__ __forceinline__ void alloc_seg(const int* __restrict__ cnt, int* __restrict__ off,
                                          int* __restrict__ cur, int n, int* __restrict__ gTot,
                                          int blk) {
    __shared__ int wsum[8];
    __shared__ int blockBase;
    const int tid = threadIdx.x, lane = tid & 31, wid = tid >> 5;
    int i = blk * 256 + tid;
    int v = (i < n) ? cnt[i] : 0;
    int x = v;
    #pragma unroll
    for (int d = 1; d < 32; d <<= 1) { int y = __shfl_up_sync(~0u, x, d); if (lane >= d) x += y; }
    if (lane == 31) wsum[wid] = x;
    __syncthreads();
    if (wid == 0) {
        int ws = (lane < 8) ? wsum[lane] : 0;
        #pragma unroll
        for (int d = 1; d < 8; d <<= 1) { int y = __shfl_up_sync(~0u, ws, d); if (lane >= d) ws += y; }
        if (lane < 8) wsum[lane] = ws;
    }
    __syncthreads();
    int excl = (x - v) + (wid > 0 ? wsum[wid - 1] : 0);
    if (tid == 0) blockBase = atomicAdd(gTot, wsum[7]);
    __syncthreads();
    if (i < n) { int base = blockBase + excl; off[i] = base; cur[i] = base; }
}

__global__ void alloc_kernel(const int* cntP, int* offP, int* curP, int nP, int* totP,
                             const int* cntS, int* offS, int* curS, int nS, int* totS,
                             int BP) {
    if ((int)blockIdx.x < BP) alloc_seg(cntP, offP, curP, nP, totP, blockIdx.x);
    else                      alloc_seg(cntS, offS, curS, nS, totS, blockIdx.x - BP);
}

__global__ void fill_kernel(const int* __restrict__ es, const int* __restrict__ ep,
                            int* __restrict__ curS, int* __restrict__ curP,
                            int* __restrict__ adjS, int* __restrict__ adjP, int E) {
    int i = blockIdx.x * blockDim.x + threadIdx.x;
    if (i >= E) return;
    int s = es[i], p = ep[i];
    int ps = atomicAdd(&curS[s], 1); adjS[ps] = p;
    int pp = atomicAdd(&curP[p], 1); adjP[pp] = s;
}

// ======================= all conversions fused (fp32 -> fp16) ================
__global__ void convert_all(const float* __restrict__ pe, const int* __restrict__ pid, int NP,
                            __half* __restrict__ play16,
                            const float* __restrict__ song, int NS, __half* __restrict__ song16,
                            const float* Wl0, const float* Wr0, const float* Wl1, const float* Wr1,
                            const float* Wl2, const float* Wr2, const float* Wl3, const float* Wr3,
                            __half* __restrict__ W16, int Bg, int Bc) {
    int b = blockIdx.x;
    if (b < Bg) {
        int t = b * blockDim.x + threadIdx.x;
        int row = t >> 5, lane = t & 31;
        if (row >= NP) return;
        float4 v = __ldg((const float4*)(pe + (size_t)pid[row] * HF) + lane);
        ((uint2*)(play16 + (size_t)row * HF))[lane] = make_uint2(pack2h(v.x, v.y), pack2h(v.z, v.w));
    } else if (b < Bg + Bc) {
        int i = (b - Bg) * blockDim.x + threadIdx.x;
        if (i >= NS * HF / 4) return;
        float4 v = __ldg((const float4*)song + i);
        ((uint2*)song16)[i] = make_uint2(pack2h(v.x, v.y), pack2h(v.z, v.w));
    } else {
        int lb = b - Bg - Bc;                    // 0..511
        int pair = lb >> 7;
        int idx = (lb & 127) * 256 + threadIdx.x;
        const float* Wl = pair == 0 ? Wl0 : pair == 1 ? Wl1 : pair == 2 ? Wl2 : Wl3;
        const float* Wr = pair == 0 ? Wr0 : pair == 1 ? Wr1 : pair == 2 ? Wr2 : Wr3;
        int k = idx & 255, n = idx >> 8;
        float w = (k < 128) ? Wl[(size_t)k * HF + n] : Wr[(size_t)(k - 128) * HF + n];
        W16[(size_t)pair * HF * 256 + (size_t)n * 256 + k] = __float2half_rn(w);
    }
}

// ======================= CSR mean-aggregation (fp16 gather, fp32 acc) ========
// Each lane owns 4 features (uint2 = 4 halves); 32 lanes cover 128. 256B/row gather.
__global__ void csr_agg(const __half* __restrict__ src,
                        const int* __restrict__ off, const int* __restrict__ cnt,
                        const int* __restrict__ adj,
                        __half* __restrict__ out16, int Ndst) {
    int warp = (blockIdx.x * blockDim.x + threadIdx.x) >> 5;
    int lane = threadIdx.x & 31;
    if (warp >= Ndst) return;
    int s0 = off[warp];
    int c  = cnt[warp];
    int s1 = s0 + c;
    float4 acc = make_float4(0.f, 0.f, 0.f, 0.f);
    for (int e = s0; e < s1; e += 32) {
        int myE = e + lane;
        int myIdx = (myE < s1) ? __ldg(adj + myE) : 0;
        int n = min(32, s1 - e);
        for (int j = 0; j < n; j++) {
            int sidx = __shfl_sync(~0u, myIdx, j);
            uint2 v = __ldg(((const uint2*)src) + (size_t)sidx * 32 + lane);
            float2 f0 = __half22float2(*(const __half2*)&v.x);
            float2 f1 = __half22float2(*(const __half2*)&v.y);
            acc.x += f0.x; acc.y += f0.y; acc.z += f1.x; acc.w += f1.y;
        }
    }
    float w = 1.0f / (float)max(c, 1);
    acc.x *= w; acc.y *= w; acc.z *= w; acc.w *= w;
    ((uint2*)(out16 + (size_t)warp * HF))[lane] = make_uint2(pack2h(acc.x, acc.y), pack2h(acc.z, acc.w));
}

// ======================= mma.sync fp16 single-pass dual GEMM =================
// out = act(A1 @ Wl + b + A2 @ Wr).  Block tile 128x128, K-concat 256 in 4
// chunks of 64 (chunks 0-1: A1, 2-3: A2).  Single fp16 pass, fp32 accumulate.
// outF and out16 are independently nullable.
#define GEMM_SMEM 32768
#define OFF_A 0
#define OFF_B 16384

__device__ __forceinline__ int sw_off(int r, int q) {
    return r * 128 + ((q ^ (r & 7)) << 4);
}

__global__ __launch_bounds__(256, 2)
void mma_dual_gemm(const __half* __restrict__ A1, const __half* __restrict__ A2,
                   const __half* __restrict__ B16,
                   const float* __restrict__ bias,
                   float* __restrict__ outF, __half* __restrict__ out16,
                   int N, int doRelu) {
    extern __shared__ char smem[];
    const uint32_t sb = smem_u32(smem);
    const int tid = threadIdx.x, wid = tid >> 5, lane = tid & 31;
    const int rowBase = blockIdx.x * 128;

    const int mBase = (wid & 3) * 32;
    const int nBase = (wid >> 2) * 64;

    float acc[2][8][4];
    #pragma unroll
    for (int mt = 0; mt < 2; mt++)
        #pragma unroll
        for (int nt = 0; nt < 8; nt++)
            #pragma unroll
            for (int j = 0; j < 4; j++) acc[mt][nt][j] = 0.f;

    const int rowA  = mBase + (lane & 15);
    const int partA = lane >> 4;
    const int swA   = rowA & 7;
    const int rowB  = nBase + ((lane >> 4) << 3) + (lane & 7);
    const int partB = (lane >> 3) & 1;
    const int swB   = rowB & 7;

    #pragma unroll 1
    for (int c = 0; c < 4; c++) {
        const __half* A = (c < 2) ? A1 : A2;
        const int kA = (c & 1) * 64;
        const int kB = c * 64;

        __syncthreads();   // previous chunk's compute done -> smem reusable
        #pragma unroll
        for (int u = 0; u < 4; u++) {
            int idx = tid + u * 256;          // 0..1023
            int r = idx >> 3, q = idx & 7;    // r: row 0..127, q: 16B quad 0..7
            int gr = rowBase + r;
            uint4 va = make_uint4(0, 0, 0, 0);
            if (gr < N) va = __ldg((const uint4*)(A + (size_t)gr * HF + kA) + q);
            uint4 vb = __ldg((const uint4*)(B16 + (size_t)r * 256 + kB) + q);
            int so = sw_off(r, q);
            *(uint4*)(smem + OFF_A + so) = va;
            *(uint4*)(smem + OFF_B + so) = vb;
        }
        __syncthreads();

        #pragma unroll
        for (int ks = 0; ks < 4; ks++) {
            uint32_t a[2][4], b[8][2];
            const int qa = ((ks * 2 + partA) ^ swA) << 4;
            const int qb = ((ks * 2 + partB) ^ swB) << 4;
            #pragma unroll
            for (int mt = 0; mt < 2; mt++)
                ldsm_x4(a[mt], sb + OFF_A + (rowA + mt * 16) * 128 + qa);
            #pragma unroll
            for (int p = 0; p < 4; p++)
                ldsm_x4(&b[p * 2][0], sb + OFF_B + (rowB + p * 16) * 128 + qb);
            #pragma unroll
            for (int mt = 0; mt < 2; mt++)
                #pragma unroll
                for (int nt = 0; nt < 8; nt++)
                    mma_f16(acc[mt][nt], a[mt], b[nt]);
        }
    }

    // ---- epilogue: bias (+relu), nullable fp32 / fp16 stores ----------------
    const int erow = lane >> 2;
    const int ecol = (lane & 3) * 2;
    #pragma unroll
    for (int mt = 0; mt < 2; mt++) {
        #pragma unroll
        for (int nt = 0; nt < 8; nt++) {
            int col = nBase + nt * 8 + ecol;
            float2 bb = *(const float2*)(bias + col);
            #pragma unroll
            for (int h = 0; h < 2; h++) {
                int gr = rowBase + mBase + mt * 16 + erow + h * 8;
                if (gr < N) {
                    float x0 = acc[mt][nt][h * 2 + 0] + bb.x;
                    float x1 = acc[mt][nt][h * 2 + 1] + bb.y;
                    if (doRelu) { x0 = fmaxf(x0, 0.f); x1 = fmaxf(x1, 0.f); }
                    if (outF)
                        *(float2*)(outF + (size_t)gr * HF + col) = make_float2(x0, x1);
                    if (out16)
                        *(uint32_t*)(out16 + (size_t)gr * HF + col) = pack2h(x0, x1);
                }
            }
        }
    }
}

// ======================= launch (fork-join multi-stream graph) ===============
extern "C" void kernel_launch(void* const* d_in, const int* in_sizes, int n_in,
                              void* d_out, int out_size) {
    const float* song_x = (const float*)d_in[0];
    const int*   pid    = (const int*)  d_in[1];
    const int*   es     = (const int*)  d_in[2];
    const int*   ep     = (const int*)  d_in[3];
    const float* pemb   = (const float*)d_in[4];
    const float* Wl1_sp = (const float*)d_in[5];
    const float* Wr1_sp = (const float*)d_in[6];
    const float* b1_sp  = (const float*)d_in[7];
    const float* Wl1_ps = (const float*)d_in[8];
    const float* Wr1_ps = (const float*)d_in[9];
    const float* b1_ps  = (const float*)d_in[10];
    const float* Wl2_sp = (const float*)d_in[11];
    const float* Wr2_sp = (const float*)d_in[12];
    const float* b2_sp  = (const float*)d_in[13];
    const float* Wl2_ps = (const float*)d_in[14];
    const float* Wr2_ps = (const float*)d_in[15];
    const float* b2_ps  = (const float*)d_in[16];

    const int NS = in_sizes[0] / HF;
    const int NP = in_sizes[1];
    const int E  = in_sizes[2];

    int *cntP, *cntS, *offP, *offS, *curP, *curS, *adjP, *adjS, *totP, *totS;
    __half *song16, *play16, *aggP16, *aggS16, *p116, *s116, *W16;
    cudaGetSymbolAddress((void**)&cntP,  g_cntP);
    cudaGetSymbolAddress((void**)&cntS,  g_cntS);
    cudaGetSymbolAddress((void**)&offP,  g_offP);
    cudaGetSymbolAddress((void**)&offS,  g_offS);
    cudaGetSymbolAddress((void**)&curP,  g_curP);
    cudaGetSymbolAddress((void**)&curS,  g_curS);
    cudaGetSymbolAddress((void**)&adjP,  g_adjP);
    cudaGetSymbolAddress((void**)&adjS,  g_adjS);
    cudaGetSymbolAddress((void**)&totP,  g_totP);
    cudaGetSymbolAddress((void**)&totS,  g_totS);
    cudaGetSymbolAddress((void**)&song16, g_song16);
    cudaGetSymbolAddress((void**)&play16, g_play16);
    cudaGetSymbolAddress((void**)&aggP16, g_aggP16);
    cudaGetSymbolAddress((void**)&aggS16, g_aggS16);
    cudaGetSymbolAddress((void**)&p116,   g_p116);
    cudaGetSymbolAddress((void**)&s116,   g_s116);
    cudaGetSymbolAddress((void**)&W16,    g_W16);

    float* out_s2 = (float*)d_out;
    float* out_p2 = (float*)d_out + (size_t)NS * HF;

    // one-time resources (no device memory involved)
    static cudaStream_t strA = 0, strB = 0;
    static cudaEvent_t evStart = 0, evFill = 0, evConv = 0, evS1 = 0, evP1 = 0, evA = 0, evB = 0;
    if (!strA) {
        cudaFuncSetAttribute(mma_dual_gemm, cudaFuncAttributeMaxDynamicSharedMemorySize, GEMM_SMEM);
        cudaStreamCreateWithFlags(&strA, cudaStreamNonBlocking);
        cudaStreamCreateWithFlags(&strB, cudaStreamNonBlocking);
        cudaEventCreateWithFlags(&evStart, cudaEventDisableTiming);
        cudaEventCreateWithFlags(&evFill,  cudaEventDisableTiming);
        cudaEventCreateWithFlags(&evConv,  cudaEventDisableTiming);
        cudaEventCreateWithFlags(&evS1,    cudaEventDisableTiming);
        cudaEventCreateWithFlags(&evP1,    cudaEventDisableTiming);
        cudaEventCreateWithFlags(&evA,     cudaEventDisableTiming);
        cudaEventCreateWithFlags(&evB,     cudaEventDisableTiming);
    }

    const int aggBlkP = (NP + 7) / 8;
    const int aggBlkS = (NS + 7) / 8;
    const int tileP = (NP + 127) / 128;
    const int tileS = (NS + 127) / 128;
    const size_t WSZ = (size_t)HF * 256;

    // ---- fork: conversions on strB, CSR build on strA ----
    cudaEventRecord(evStart, 0);
    cudaStreamWaitEvent(strB, evStart, 0);
    cudaStreamWaitEvent(strA, evStart, 0);

    {   // strB: conversions (independent of CSR build)
        int Bg = (NP * 32 + 255) / 256;
        int Bc = (NS * HF / 4 + 255) / 256;
        convert_all<<<Bg + Bc + 512, 256, 0, strB>>>(pemb, pid, NP, play16,
                                                     song_x, NS, song16,
                                                     Wl1_sp, Wr1_sp, Wl1_ps, Wr1_ps,
                                                     Wl2_sp, Wr2_sp, Wl2_ps, Wr2_ps,
                                                     W16, Bg, Bc);
        cudaEventRecord(evConv, strB);
    }

    // strA: CSR build chain
    zero_cnt<<<(NS + 255) / 256, 256, 0, strA>>>(cntP, NP, cntS, NS, totP, totS);
    count_kernel<<<(E + 255) / 256, 256, 0, strA>>>(es, ep, cntS, cntP, E);
    {
        int BP = (NP + 255) / 256, BS = (NS + 255) / 256;
        alloc_kernel<<<BP + BS, 256, 0, strA>>>(cntP, offP, curP, NP, totP,
                                                cntS, offS, curS, NS, totS, BP);
    }
    fill_kernel<<<(E + 255) / 256, 256, 0, strA>>>(es, ep, curS, curP, adjS, adjP, E);
    cudaEventRecord(evFill, strA);

    // ---- layer 1: S-chain on strA, P-chain on strB ----
    // aggS gathers play16 (needs evConv); gemmS needs song16 (evConv, already waited)
    cudaStreamWaitEvent(strA, evConv, 0);
    csr_agg<<<aggBlkS, 256, 0, strA>>>(play16, offS, cntS, adjS, aggS16, NS);
    mma_dual_gemm<<<tileS, 256, GEMM_SMEM, strA>>>(aggS16, song16, W16 + 1 * WSZ, b1_ps,
                                                   ((float*)0), s116, NS, 1);
    cudaEventRecord(evS1, strA);

    // aggP gathers song16 (needs evConv) + CSR (evFill)
    cudaStreamWaitEvent(strB, evFill, 0);
    csr_agg<<<aggBlkP, 256, 0, strB>>>(song16, offP, cntP, adjP, aggP16, NP);
    mma_dual_gemm<<<tileP, 256, GEMM_SMEM, strB>>>(aggP16, play16, W16 + 0 * WSZ, b1_sp,
                                                   ((float*)0), p116, NP, 1);
    cudaEventRecord(evP1, strB);

    // ---- layer 2: crossed dependencies ----
    // S-side layer 2 gathers p116 (strB) ; dense operand s116 (in-stream)
    cudaStreamWaitEvent(strA, evP1, 0);
    csr_agg<<<aggBlkS, 256, 0, strA>>>(p116, offS, cntS, adjS, aggS16, NS);
    mma_dual_gemm<<<tileS, 256, GEMM_SMEM, strA>>>(aggS16, s116, W16 + 3 * WSZ, b2_ps,
                                                   out_s2, ((__half*)0), NS, 0);
    cudaEventRecord(evA, strA);

    // P-side layer 2 gathers s116 (strA) ; dense operand p116 (in-stream)
    cudaStreamWaitEvent(strB, evS1, 0);
    csr_agg<<<aggBlkP, 256, 0, strB>>>(s116, offP, cntP, adjP, aggP16, NP);
    mma_dual_gemm<<<tileP, 256, GEMM_SMEM, strB>>>(aggP16, p116, W16 + 2 * WSZ, b2_sp,
                                                   out_p2, ((__half*)0), NP, 0);
    cudaEventRecord(evB, strB);

    // ---- join back to the capture origin stream ----
    cudaStreamWaitEvent(0, evA, 0);
    cudaStreamWaitEvent(0, evB, 0);
}